// round 13
// baseline (speedup 1.0000x reference)
#include <cuda_runtime.h>
#include <cuda_fp16.h>
#include <stdint.h>
#include <math.h>

// ---------------------------------------------------------------- constants
#define S_LEN   1272
#define S_PAD   1280
#define D_MODEL 512
#define QKV_N   1536
#define FF_DIM  2048
#define NLAYERS 8
#define UB      248
#define LN_EPS  1e-3f
#define LO_SCALE    2048.0f
#define LO_INV      4.8828125e-4f   // 1/2048

// ---------------------------------------------------------------- scratch
__device__ float g_hn  [S_PAD * D_MODEL];
__device__ float g_attn[S_PAD * D_MODEL];
__device__ float g_ff2a[S_PAD * D_MODEL];
__device__ float g_ff2b[3 * S_PAD * D_MODEL];   // split-K partials (reused)
__device__ float g_qkv [S_PAD * QKV_N];
__device__ float g_bqkv[NLAYERS * QKV_N];

__device__ __half g_hn_h[S_PAD * D_MODEL];
__device__ __half g_y_h [S_PAD * D_MODEL];
__device__ __half g_ff_h[S_PAD * FF_DIM];

__device__ __half g_wqkv_hi[NLAYERS * QKV_N * D_MODEL];
__device__ __half g_wqkv_lo[NLAYERS * QKV_N * D_MODEL];   // scaled by 2^11
__device__ __half g_w1t_hi [NLAYERS * FF_DIM * D_MODEL];
__device__ __half g_w1t_lo [NLAYERS * FF_DIM * D_MODEL];
__device__ __half g_w2t_hi [NLAYERS * D_MODEL * FF_DIM];
__device__ __half g_w2t_lo [NLAYERS * D_MODEL * FF_DIM];

// ---------------------------------------------------------------- PTX utils
__device__ __forceinline__ uint32_t smem_u32(const void* p) {
    uint32_t a;
    asm("{ .reg .u64 t; cvta.to.shared.u64 t, %1; cvt.u32.u64 %0, t; }"
        : "=r"(a) : "l"(p));
    return a;
}

#define CP16(s, g) \
    asm volatile("cp.async.cg.shared.global [%0], [%1], 16;" :: "r"(s), "l"(g))
#define CP_COMMIT() asm volatile("cp.async.commit_group;" ::: "memory")
#define CP_WAIT1()  asm volatile("cp.async.wait_group 1;" ::: "memory")

#define LDSM4(r0, r1, r2, r3, a) \
    asm volatile("ldmatrix.sync.aligned.m8n8.x4.shared.b16 {%0,%1,%2,%3}, [%4];" \
                 : "=r"(r0), "=r"(r1), "=r"(r2), "=r"(r3) : "r"(a))

#define MMA16816(c, a, b0, b1)                                                \
    asm volatile("mma.sync.aligned.m16n8k16.row.col.f32.f16.f16.f32 "         \
                 "{%0,%1,%2,%3}, {%4,%5,%6,%7}, {%8,%9}, {%0,%1,%2,%3};"      \
                 : "+f"((c)[0]), "+f"((c)[1]), "+f"((c)[2]), "+f"((c)[3])     \
                 : "r"((a)[0]), "r"((a)[1]), "r"((a)[2]), "r"((a)[3]),        \
                   "r"(b0), "r"(b1))

// ----------------------------------------------------------- block LN reduce
__device__ __forceinline__ float2 block_meanvar(float x0, float x1,
                                                float* shs, float* shss,
                                                float* smu, float* srstd)
{
    __syncthreads();
    int t = threadIdx.x;
    float s  = x0 + x1;
    float ss = x0 * x0 + x1 * x1;
    #pragma unroll
    for (int o = 16; o; o >>= 1) {
        s  += __shfl_xor_sync(0xffffffffu, s, o);
        ss += __shfl_xor_sync(0xffffffffu, ss, o);
    }
    int w = t >> 5, lane = t & 31;
    if (lane == 0) { shs[w] = s; shss[w] = ss; }
    __syncthreads();
    if (t == 0) {
        float a = 0.f, c = 0.f;
        #pragma unroll
        for (int i = 0; i < 8; ++i) { a += shs[i]; c += shss[i]; }
        float mu  = a * (1.0f / D_MODEL);
        float var = c * (1.0f / D_MODEL) - mu * mu;
        *smu = mu;
        *srstd = rsqrtf(var + LN_EPS);
    }
    __syncthreads();
    return make_float2(*smu, *srstd);
}

// ---------------------------------------------------------------- LayerNorm
__global__ void __launch_bounds__(256) ln_kernel(
    const float* __restrict__ in, const float* __restrict__ gamma,
    const float* __restrict__ beta, float* __restrict__ out,
    __half* __restrict__ outH)
{
    __shared__ float shs[8], shss[8], smu, srstd;
    int r = blockIdx.x;
    int t = threadIdx.x;
    const float* row = in + (size_t)r * D_MODEL;
    float x0 = row[t], x1 = row[t + 256];
    float2 mv = block_meanvar(x0, x1, shs, shss, &smu, &srstd);
    float y0 = (x0 - mv.x) * mv.y * gamma[t]       + beta[t];
    float y1 = (x1 - mv.x) * mv.y * gamma[t + 256] + beta[t + 256];
    size_t o0 = (size_t)r * D_MODEL + t;
    if (out) { out[o0] = y0; out[o0 + 256] = y1; }
    outH[o0]       = __float2half_rn(y0);
    outH[o0 + 256] = __float2half_rn(y1);
}

// Fused: t = LN2(inA + inB0 + inB1 + inB2); optional write; hn = LN_in(t).
__global__ void __launch_bounds__(256) ln2_lnin_kernel(
    const float* __restrict__ inA, const float* __restrict__ inB,
    const float* __restrict__ g2, const float* __restrict__ b2,
    float* __restrict__ outT,
    const float* __restrict__ gi, const float* __restrict__ bi,
    float* __restrict__ hn, __half* __restrict__ hnH)
{
    __shared__ float shs[8], shss[8], smu, srstd;
    int r = blockIdx.x;
    int t = threadIdx.x;
    size_t o0 = (size_t)r * D_MODEL + t;
    const size_t PS = (size_t)S_PAD * D_MODEL;
    float x0 = inA[o0]       + inB[o0]       + inB[o0 + PS]       + inB[o0 + 2 * PS];
    float x1 = inA[o0 + 256] + inB[o0 + 256] + inB[o0 + PS + 256] + inB[o0 + 2 * PS + 256];
    float2 mv = block_meanvar(x0, x1, shs, shss, &smu, &srstd);
    float t0 = (x0 - mv.x) * mv.y * g2[t]       + b2[t];
    float t1 = (x1 - mv.x) * mv.y * g2[t + 256] + b2[t + 256];
    if (outT) { outT[o0] = t0; outT[o0 + 256] = t1; }
    if (gi) {
        float2 mv2 = block_meanvar(t0, t1, shs, shss, &smu, &srstd);
        float u0 = (t0 - mv2.x) * mv2.y * gi[t]       + bi[t];
        float u1 = (t1 - mv2.x) * mv2.y * gi[t + 256] + bi[t + 256];
        hn[o0] = u0; hn[o0 + 256] = u1;
        hnH[o0]       = __float2half_rn(u0);
        hnH[o0 + 256] = __float2half_rn(u1);
    }
}

// ------------------------------------- single-launch weight prep (all layers)
__device__ __forceinline__ void tile64_transpose_split(
    const float* __restrict__ src, __half* __restrict__ dhi,
    __half* __restrict__ dlo, int K, int N, int n0, int k0, int tid)
{
    __shared__ float t[64][66];
    int tx = tid & 31, ty = tid >> 5;
    #pragma unroll
    for (int kk = ty; kk < 64; kk += 8) {
        float2 v = *reinterpret_cast<const float2*>(
            src + (size_t)(k0 + kk) * N + n0 + 2 * tx);
        t[2 * tx][kk]     = v.x;
        t[2 * tx + 1][kk] = v.y;
    }
    __syncthreads();
    #pragma unroll
    for (int it = 0; it < 8; ++it) {
        int nn = it * 8 + ty;
        float2 v = *reinterpret_cast<const float2*>(&t[nn][2 * tx]);
        __half h0 = __float2half_rn(v.x);
        __half h1 = __float2half_rn(v.y);
        __half2 hh; hh.x = h0; hh.y = h1;
        __half2 ll;
        ll.x = __float2half_rn((v.x - __half2float(h0)) * LO_SCALE);
        ll.y = __float2half_rn((v.y - __half2float(h1)) * LO_SCALE);
        size_t o = (size_t)(n0 + nn) * K + k0 + 2 * tx;
        *reinterpret_cast<__half2*>(dhi + o) = hh;
        *reinterpret_cast<__half2*>(dlo + o) = ll;
    }
}

#define PREP_PER_LAYER 704
#define PREP_TRANS_BLOCKS (PREP_PER_LAYER * NLAYERS)
#define PREP_BIAS_BLOCKS 48
#define PREP_BLOCKS (PREP_TRANS_BLOCKS + PREP_BIAS_BLOCKS)

__global__ void __launch_bounds__(256) prep_all(
    const float* __restrict__ wq, const float* __restrict__ wk,
    const float* __restrict__ wv, const float* __restrict__ w1,
    const float* __restrict__ w2,
    const float* __restrict__ bq, const float* __restrict__ bk,
    const float* __restrict__ bv,
    __half* __restrict__ wqkv_hi, __half* __restrict__ wqkv_lo,
    __half* __restrict__ w1t_hi,  __half* __restrict__ w1t_lo,
    __half* __restrict__ w2t_hi,  __half* __restrict__ w2t_lo,
    float* __restrict__ bqkv)
{
    int id = blockIdx.x;
    int tid = threadIdx.x;
    if (id >= PREP_TRANS_BLOCKS) {
        int i = (id - PREP_TRANS_BLOCKS) * 256 + tid;
        int l = i / QKV_N, c = i % QKV_N;
        float v;
        if (c < 512)       v = bq[l * 512 + c];
        else if (c < 1024) v = bk[l * 512 + c - 512];
        else               v = bv[l * 512 + c - 1024];
        bqkv[i] = v;
        return;
    }
    int l = id / PREP_PER_LAYER;
    int r = id % PREP_PER_LAYER;
    if (r < 192) {
        int which = r >> 6;
        int t = r & 63;
        const float* src = (which == 0) ? wq : (which == 1) ? wk : wv;
        src += (size_t)l * 512 * 512;
        size_t doff = (size_t)l * QKV_N * 512 + (size_t)which * 512 * 512;
        tile64_transpose_split(src, wqkv_hi + doff, wqkv_lo + doff,
                               512, 512, (t & 7) * 64, (t >> 3) * 64, tid);
    } else if (r < 448) {
        int t = r - 192;
        const float* src = w1 + (size_t)l * 512 * 2048;
        size_t doff = (size_t)l * FF_DIM * 512;
        tile64_transpose_split(src, w1t_hi + doff, w1t_lo + doff,
                               512, 2048, (t & 31) * 64, (t >> 5) * 64, tid);
    } else {
        int t = r - 448;
        const float* src = w2 + (size_t)l * 2048 * 512;
        size_t doff = (size_t)l * D_MODEL * FF_DIM;
        tile64_transpose_split(src, w2t_hi + doff, w2t_lo + doff,
                               2048, 512, (t & 7) * 64, (t >> 3) * 64, tid);
    }
}

// ------------------------------------------------------------- mma.sync GEMM
// fp16 2-pass: C = A*Bhi + 2^-11 * (A*Blo_scaled). BM=128, BN=64, BK=32,
// 3-stage cp.async, 8 warps (4x2), dual fp32 accumulators.
#define A_OFF   0
#define BHI_OFF 8192
#define BLO_OFF 12288
#define STAGE_BYTES 16384
#define GEMM_SMEM (3 * STAGE_BYTES)

__device__ __forceinline__ uint32_t phys(int r, int c) {
    return (uint32_t)(r * 64 + ((c ^ (r & 3)) << 4));
}

__global__ void __launch_bounds__(256, 2) gemm_tc(
    const __half* __restrict__ A,
    const __half* __restrict__ Bhi, const __half* __restrict__ Blo,
    const float* __restrict__ bias, const float* __restrict__ res,
    float* __restrict__ outF, float* __restrict__ outF2,
    __half* __restrict__ outH, int Klen, int ldK, int N)
{
    extern __shared__ char smraw[];
    const uint32_t sb = smem_u32(smraw);

    const int tid  = threadIdx.x;
    const int lane = tid & 31;
    const int wid  = tid >> 5;
    const int wm   = wid >> 1;
    const int wn   = wid & 1;
    const int m0   = blockIdx.x * 128;
    const int n0   = blockIdx.y * 64;
    const int kz   = blockIdx.z;
    const int koff = kz * Klen;

    const __half* a0 = A   + (size_t)m0 * ldK + koff;
    const __half* b0 = Bhi + (size_t)n0 * ldK + koff;
    const __half* b1 = Blo + (size_t)n0 * ldK + koff;

    const int r0c = tid >> 2, cc = tid & 3;
    const int r1c = r0c + 64;
    const uint32_t s0 = phys(r0c, cc), s1 = phys(r1c, cc);

    float acc[2][4][4], accL[2][4][4];
    #pragma unroll
    for (int i = 0; i < 2; ++i)
        #pragma unroll
        for (int j = 0; j < 4; ++j)
            #pragma unroll
            for (int k = 0; k < 4; ++k) { acc[i][j][k] = 0.f; accL[i][j][k] = 0.f; }

    const int NC = Klen >> 5;

    auto issue = [&](int c) {
        const uint32_t st = sb + (uint32_t)(c % 3) * STAGE_BYTES;
        const int k0 = c << 5;
        const size_t go0 = (size_t)r0c * ldK + k0 + cc * 8;
        const size_t go1 = (size_t)r1c * ldK + k0 + cc * 8;
        CP16(st + A_OFF + s0,   a0 + go0);
        CP16(st + A_OFF + s1,   a0 + go1);
        CP16(st + BHI_OFF + s0, b0 + go0);
        CP16(st + BLO_OFF + s0, b1 + go0);
    };

    issue(0); CP_COMMIT();
    issue(1); CP_COMMIT();

    const int lr = lane & 15, lc = lane >> 4;
    const int bg = lane >> 3, bi = lane & 7;
    const int arow0 = wm * 32 + lr;
    const int arow1 = arow0 + 16;
    const int browb = wn * 32 + ((bg >> 1) << 3) + bi;

    for (int c = 0; c < NC; ++c) {
        CP_WAIT1();
        __syncthreads();

        const uint32_t st = sb + (uint32_t)(c % 3) * STAGE_BYTES;
        #pragma unroll
        for (int ks = 0; ks < 2; ++ks) {
            const int ca = ks * 2 + lc;
            const int cb = ks * 2 + (bg & 1);
            uint32_t a0f[4], a1f[4];
            uint32_t bh[4], bh2[4], bl[4], bl2[4];
            LDSM4(a0f[0], a0f[1], a0f[2], a0f[3], st + A_OFF + phys(arow0, ca));
            LDSM4(a1f[0], a1f[1], a1f[2], a1f[3], st + A_OFF + phys(arow1, ca));
            LDSM4(bh[0], bh[1], bh[2], bh[3],     st + BHI_OFF + phys(browb, cb));
            LDSM4(bh2[0], bh2[1], bh2[2], bh2[3], st + BHI_OFF + phys(browb + 16, cb));
            LDSM4(bl[0], bl[1], bl[2], bl[3],     st + BLO_OFF + phys(browb, cb));
            LDSM4(bl2[0], bl2[1], bl2[2], bl2[3], st + BLO_OFF + phys(browb + 16, cb));

            MMA16816(acc[0][0], a0f, bh[0],  bh[1]);
            MMA16816(acc[0][1], a0f, bh[2],  bh[3]);
            MMA16816(acc[0][2], a0f, bh2[0], bh2[1]);
            MMA16816(acc[0][3], a0f, bh2[2], bh2[3]);
            MMA16816(acc[1][0], a1f, bh[0],  bh[1]);
            MMA16816(acc[1][1], a1f, bh[2],  bh[3]);
            MMA16816(acc[1][2], a1f, bh2[0], bh2[1]);
            MMA16816(acc[1][3], a1f, bh2[2], bh2[3]);

            MMA16816(accL[0][0], a0f, bl[0],  bl[1]);
            MMA16816(accL[0][1], a0f, bl[2],  bl[3]);
            MMA16816(accL[0][2], a0f, bl2[0], bl2[1]);
            MMA16816(accL[0][3], a0f, bl2[2], bl2[3]);
            MMA16816(accL[1][0], a1f, bl[0],  bl[1]);
            MMA16816(accL[1][1], a1f, bl[2],  bl[3]);
            MMA16816(accL[1][2], a1f, bl2[0], bl2[1]);
            MMA16816(accL[1][3], a1f, bl2[2], bl2[3]);
        }
        if (c + 2 < NC) issue(c + 2);
        CP_COMMIT();
    }

    // ------------------------------------------------------------- epilogue
    const int erow = (lane >> 2);
    const int ecol = (lane & 3) * 2;
    #pragma unroll
    for (int mt = 0; mt < 2; ++mt) {
        #pragma unroll
        for (int half = 0; half < 2; ++half) {
            const int row = m0 + wm * 32 + mt * 16 + erow + half * 8;
            #pragma unroll
            for (int nt = 0; nt < 4; ++nt) {
                const int col = n0 + wn * 32 + nt * 8 + ecol;
                float v0 = acc[mt][nt][half * 2 + 0] + accL[mt][nt][half * 2 + 0] * LO_INV;
                float v1 = acc[mt][nt][half * 2 + 1] + accL[mt][nt][half * 2 + 1] * LO_INV;
                if (kz >= 1) {
                    *reinterpret_cast<float2*>(
                        outF2 + (size_t)(kz - 1) * S_PAD * D_MODEL +
                        (size_t)row * N + col) = make_float2(v0, v1);
                    continue;
                }
                v0 += __ldg(bias + col);
                v1 += __ldg(bias + col + 1);
                if (res) {
                    const float2 r2 = *reinterpret_cast<const float2*>(
                        res + (size_t)row * N + col);
                    v0 += r2.x; v1 += r2.y;
                }
                if (outF)
                    *reinterpret_cast<float2*>(outF + (size_t)row * N + col) =
                        make_float2(v0, v1);
                if (outH) {
                    __half2 hh;
                    hh.x = __float2half_rn(v0);
                    hh.y = __float2half_rn(v1);
                    *reinterpret_cast<__half2*>(outH + (size_t)row * N + col) = hh;
                }
            }
        }
    }
}

// ---------------------------------------------- chunked sparse attention v4
// grid (32, 8, 2): chunk, head, query-half. K/V staged per block (duplicated
// across z — cheap); Q staged for this half only. v3 register blocking with
// <=2 queries per warp. 512 threads.
#define ATTN_THREADS 512

__global__ void __launch_bounds__(ATTN_THREADS) attn_chunk_kernel(
    const float* __restrict__ QKV, const float* __restrict__ QKV2,
    const float* __restrict__ hn, float* __restrict__ attnOut)
{
    __shared__ float Ks[64][61];
    __shared__ float Vs[60][68];
    __shared__ float Qs[20][64];

    const int i    = blockIdx.x;
    const int h    = blockIdx.y;
    const int z    = blockIdx.z;
    const int tid  = threadIdx.x;
    const int w    = tid >> 5;           // 0..15
    const int lane = tid & 31;
    const int hoff = h * 64;

    const int bodyLo = max(0, 32 * i - 20);
    const int nb     = 32 * (i + 1) - bodyLo;
    const int nrc    = (i < 31) ? 8 : 0;
    const int nk     = nrc + nb;
    const int nq     = 32 + nrc;
    const int nqh    = nq >> 1;          // 20 (i<31) or 16
    const int qbase  = z * nqh;

    // stage K (transposed) and V (summing split-K halves)
    for (int e = tid; e < nk * 32; e += ATTN_THREADS) {
        int j = e >> 5, d = (e & 31) * 2;
        int kg = (j < nrc) ? (8 * i + j) : (UB + bodyLo + (j - nrc));
        size_t base = (size_t)kg * QKV_N + hoff + d;
        float2 k0 = *reinterpret_cast<const float2*>(QKV  + base + 512);
        float2 k1 = *reinterpret_cast<const float2*>(QKV2 + base + 512);
        float2 v0 = *reinterpret_cast<const float2*>(QKV  + base + 1024);
        float2 v1 = *reinterpret_cast<const float2*>(QKV2 + base + 1024);
        Ks[d][j]     = k0.x + k1.x;
        Ks[d + 1][j] = k0.y + k1.y;
        Vs[j][d]     = v0.x + v1.x;
        Vs[j][d + 1] = v0.y + v1.y;
    }
    // stage this half's Q (scale folded, summing split-K halves)
    for (int e = tid; e < nqh * 32; e += ATTN_THREADS) {
        int qq = e >> 5, d = (e & 31) * 2;
        int qg = qbase + qq;
        int row = (qg < nrc) ? (8 * i + qg) : (UB + 32 * i + (qg - nrc));
        size_t base = (size_t)row * QKV_N + hoff + d;
        float2 q0 = *reinterpret_cast<const float2*>(QKV  + base);
        float2 q1 = *reinterpret_cast<const float2*>(QKV2 + base);
        Qs[qq][d]     = (q0.x + q1.x) * 0.125f;
        Qs[qq][d + 1] = (q0.y + q1.y) * 0.125f;
    }
    __syncthreads();

    const int lim1 = nk - 32;
    // queries for this warp (local): w, w+16  (nqw <= 2)
    const int nqw = (nqh - w + 15) >> 4;

    // ---- scores: one d-sweep, K loads shared across queries
    float s0[2] = {0.f, 0.f}, s1[2] = {0.f, 0.f};
    #pragma unroll 8
    for (int d = 0; d < 64; ++d) {
        float k0 = Ks[d][lane];
        float k1 = Ks[d][lane + 32];
        #pragma unroll
        for (int t = 0; t < 2; ++t) {
            if (t < nqw) {
                float qd = Qs[w + 16 * t][d];
                s0[t] = fmaf(qd, k0, s0[t]);
                s1[t] = fmaf(qd, k1, s1[t]);
            }
        }
    }

    // ---- per-query softmax
    float e0[2], e1[2], inv[2];
    #pragma unroll
    for (int t = 0; t < 2; ++t) {
        if (t >= nqw) { e0[t] = 0.f; e1[t] = 0.f; inv[t] = 0.f; continue; }
        float a0 = s0[t];
        float a1 = (lane < lim1) ? s1[t] : -1e30f;
        float m = fmaxf(a0, a1);
        #pragma unroll
        for (int o = 16; o; o >>= 1) m = fmaxf(m, __shfl_xor_sync(0xffffffffu, m, o));
        e0[t] = __expf(a0 - m);
        e1[t] = (lane < lim1) ? __expf(a1 - m) : 0.f;
        float ssum = e0[t] + e1[t];
        #pragma unroll
        for (int o = 16; o; o >>= 1) ssum += __shfl_xor_sync(0xffffffffu, ssum, o);
        inv[t] = 1.0f / ssum;
    }

    // ---- PV: one key-sweep, V loads shared across queries
    float o0[2] = {0.f, 0.f}, o1[2] = {0.f, 0.f};
    #pragma unroll 4
    for (int jj = 0; jj < 32; ++jj) {
        float2 v = *reinterpret_cast<const float2*>(&Vs[jj][2 * lane]);
        #pragma unroll
        for (int t = 0; t < 2; ++t) {
            float p = __shfl_sync(0xffffffffu, e0[t], jj);
            o0[t] = fmaf(p, v.x, o0[t]);
            o1[t] = fmaf(p, v.y, o1[t]);
        }
    }
    for (int jj = 0; jj < lim1; ++jj) {
        float2 v = *reinterpret_cast<const float2*>(&Vs[jj + 32][2 * lane]);
        #pragma unroll
        for (int t = 0; t < 2; ++t) {
            float p = __shfl_sync(0xffffffffu, e1[t], jj);
            o0[t] = fmaf(p, v.x, o0[t]);
            o1[t] = fmaf(p, v.y, o1[t]);
        }
    }

    // ---- write
    #pragma unroll
    for (int t = 0; t < 2; ++t) {
        if (t >= nqw) continue;
        const int qg = qbase + w + 16 * t;
        const int row = (qg < nrc) ? (8 * i + qg) : (UB + 32 * i + (qg - nrc));
        const size_t off = (size_t)row * D_MODEL + hoff + 2 * lane;
        const float2 hv = *reinterpret_cast<const float2*>(hn + off);
        *reinterpret_cast<float2*>(attnOut + off) =
            make_float2(o0[t] * inv[t] + hv.x, o1[t] * inv[t] + hv.y);
    }
}

// ------------------------------------------------------------------- driver
extern "C" void kernel_launch(void* const* d_in, const int* in_sizes, int n_in,
                              void* d_out, int out_size)
{
    (void)in_sizes; (void)n_in; (void)out_size;

    const float* x      = (const float*)d_in[0];
    const float* lnin_s = (const float*)d_in[2];
    const float* lnin_b = (const float*)d_in[3];
    const float* wq     = (const float*)d_in[4];
    const float* bq     = (const float*)d_in[5];
    const float* wk     = (const float*)d_in[6];
    const float* bk     = (const float*)d_in[7];
    const float* wv     = (const float*)d_in[8];
    const float* bv     = (const float*)d_in[9];
    const float* ln1_s  = (const float*)d_in[10];
    const float* ln1_b  = (const float*)d_in[11];
    const float* w1     = (const float*)d_in[12];
    const float* b1     = (const float*)d_in[13];
    const float* w2     = (const float*)d_in[14];
    const float* b2     = (const float*)d_in[15];
    const float* ln2_s  = (const float*)d_in[16];
    const float* ln2_b  = (const float*)d_in[17];
    float* out = (float*)d_out;

    float *p_hn, *p_attn, *p_ff2a, *p_ff2b, *p_qkv, *p_bqkv;
    __half *p_hn_h, *p_y_h, *p_ff_h;
    __half *p_wqkv_hi, *p_wqkv_lo, *p_w1t_hi, *p_w1t_lo, *p_w2t_hi, *p_w2t_lo;
    cudaGetSymbolAddress((void**)&p_hn,    g_hn);
    cudaGetSymbolAddress((void**)&p_attn,  g_attn);
    cudaGetSymbolAddress((void**)&p_ff2a,  g_ff2a);
    cudaGetSymbolAddress((void**)&p_ff2b,  g_ff2b);
    cudaGetSymbolAddress((void**)&p_qkv,   g_qkv);
    cudaGetSymbolAddress((void**)&p_bqkv,  g_bqkv);
    cudaGetSymbolAddress((void**)&p_hn_h,  g_hn_h);
    cudaGetSymbolAddress((void**)&p_y_h,   g_y_h);
    cudaGetSymbolAddress((void**)&p_ff_h,  g_ff_h);
    cudaGetSymbolAddress((void**)&p_wqkv_hi, g_wqkv_hi);
    cudaGetSymbolAddress((void**)&p_wqkv_lo, g_wqkv_lo);
    cudaGetSymbolAddress((void**)&p_w1t_hi,  g_w1t_hi);
    cudaGetSymbolAddress((void**)&p_w1t_lo,  g_w1t_lo);
    cudaGetSymbolAddress((void**)&p_w2t_hi,  g_w2t_hi);
    cudaGetSymbolAddress((void**)&p_w2t_lo,  g_w2t_lo);

    cudaFuncSetAttribute(gemm_tc, cudaFuncAttributeMaxDynamicSharedMemorySize,
                         GEMM_SMEM);

    dim3 blk(256);
    prep_all<<<PREP_BLOCKS, blk>>>(wq, wk, wv, w1, w2, bq, bk, bv,
                                   p_wqkv_hi, p_wqkv_lo, p_w1t_hi, p_w1t_lo,
                                   p_w2t_hi, p_w2t_lo, p_bqkv);

    const int MT = S_PAD / 128;   // 10
    for (int l = 0; l < NLAYERS; ++l) {
        size_t oD = (size_t)l * D_MODEL;
        size_t oF = (size_t)l * FF_DIM;

        if (l == 0)
            ln_kernel<<<S_LEN, blk>>>(x, lnin_s, lnin_b, p_hn, p_hn_h);

        // fused QKV split-K=2: BN=64, grid 10x24x2 = 480
        gemm_tc<<<dim3(MT, QKV_N / 64, 2), blk, GEMM_SMEM>>>(
            p_hn_h,
            p_wqkv_hi + (size_t)l * QKV_N * 512, p_wqkv_lo + (size_t)l * QKV_N * 512,
            p_bqkv + (size_t)l * QKV_N, nullptr,
            p_qkv, p_ff2b, nullptr, 256, 512, QKV_N);
        // chunked sparse attention v4 (+ residual onto hn), grid 32x8x2
        attn_chunk_kernel<<<dim3(32, 8, 2), ATTN_THREADS>>>(p_qkv, p_ff2b,
                                                            p_hn, p_attn);
        // ln1 -> y fp16
        ln_kernel<<<S_LEN, blk>>>(p_attn, ln1_s + oD, ln1_b + oD,
                                  nullptr, p_y_h);
        // FFN1: BN=64, full K, grid 10x32 = 320
        gemm_tc<<<dim3(MT, FF_DIM / 64), blk, GEMM_SMEM>>>(
            p_y_h,
            p_w1t_hi + (size_t)l * FF_DIM * 512, p_w1t_lo + (size_t)l * FF_DIM * 512,
            b1 + oF, nullptr,
            nullptr, nullptr, p_ff_h, 512, 512, FF_DIM);
        // FFN2: BN=64, split-K=4, grid 10x8x4 = 320
        gemm_tc<<<dim3(MT, D_MODEL / 64, 4), blk, GEMM_SMEM>>>(
            p_ff_h,
            p_w2t_hi + (size_t)l * D_MODEL * FF_DIM, p_w2t_lo + (size_t)l * D_MODEL * FF_DIM,
            b2 + oD, p_attn,
            p_ff2a, p_ff2b, nullptr, 512, FF_DIM, D_MODEL);
        if (l < NLAYERS - 1) {
            ln2_lnin_kernel<<<S_LEN, blk>>>(
                p_ff2a, p_ff2b, ln2_s + oD, ln2_b + oD, nullptr,
                lnin_s + oD + D_MODEL, lnin_b + oD + D_MODEL,
                p_hn, p_hn_h);
        } else {
            ln2_lnin_kernel<<<S_LEN, blk>>>(
                p_ff2a, p_ff2b, ln2_s + oD, ln2_b + oD, out,
                nullptr, nullptr, nullptr, nullptr);
        }
    }
}

// round 14
// speedup vs baseline: 1.0761x; 1.0761x over previous
#include <cuda_runtime.h>
#include <cuda_fp16.h>
#include <stdint.h>
#include <math.h>

// ---------------------------------------------------------------- constants
#define S_LEN   1272
#define S_PAD   1280
#define D_MODEL 512
#define QKV_N   1536
#define FF_DIM  2048
#define NLAYERS 8
#define UB      248
#define LN_EPS  1e-3f
#define LO_SCALE    2048.0f
#define LO_INV      4.8828125e-4f   // 1/2048

// ---------------------------------------------------------------- scratch
__device__ float g_hn  [S_PAD * D_MODEL];
__device__ float g_attn[S_PAD * D_MODEL];
__device__ float g_ff2a[S_PAD * D_MODEL];
__device__ float g_ff2b[3 * S_PAD * D_MODEL];   // split-K partials (reused)
__device__ float g_qkv [S_PAD * QKV_N];
__device__ float g_bqkv[NLAYERS * QKV_N];

__device__ __half g_hn_h[S_PAD * D_MODEL];
__device__ __half g_y_h [S_PAD * D_MODEL];
__device__ __half g_ff_h[S_PAD * FF_DIM];

__device__ __half g_wqkv_hi[NLAYERS * QKV_N * D_MODEL];
__device__ __half g_wqkv_lo[NLAYERS * QKV_N * D_MODEL];   // scaled by 2^11
__device__ __half g_w1t_hi [NLAYERS * FF_DIM * D_MODEL];
__device__ __half g_w1t_lo [NLAYERS * FF_DIM * D_MODEL];
__device__ __half g_w2t_hi [NLAYERS * D_MODEL * FF_DIM];
__device__ __half g_w2t_lo [NLAYERS * D_MODEL * FF_DIM];

// ---------------------------------------------------------------- PTX utils
__device__ __forceinline__ uint32_t smem_u32(const void* p) {
    uint32_t a;
    asm("{ .reg .u64 t; cvta.to.shared.u64 t, %1; cvt.u32.u64 %0, t; }"
        : "=r"(a) : "l"(p));
    return a;
}

#define CP16(s, g) \
    asm volatile("cp.async.cg.shared.global [%0], [%1], 16;" :: "r"(s), "l"(g))
#define CP_COMMIT() asm volatile("cp.async.commit_group;" ::: "memory")
#define CP_WAIT2()  asm volatile("cp.async.wait_group 2;" ::: "memory")

#define LDSM4(r0, r1, r2, r3, a) \
    asm volatile("ldmatrix.sync.aligned.m8n8.x4.shared.b16 {%0,%1,%2,%3}, [%4];" \
                 : "=r"(r0), "=r"(r1), "=r"(r2), "=r"(r3) : "r"(a))

#define MMA16816(c, a, b0, b1)                                                \
    asm volatile("mma.sync.aligned.m16n8k16.row.col.f32.f16.f16.f32 "         \
                 "{%0,%1,%2,%3}, {%4,%5,%6,%7}, {%8,%9}, {%0,%1,%2,%3};"      \
                 : "+f"((c)[0]), "+f"((c)[1]), "+f"((c)[2]), "+f"((c)[3])     \
                 : "r"((a)[0]), "r"((a)[1]), "r"((a)[2]), "r"((a)[3]),        \
                   "r"(b0), "r"(b1))

// ----------------------------------------------------------- block LN reduce
__device__ __forceinline__ float2 block_meanvar(float x0, float x1,
                                                float* shs, float* shss,
                                                float* smu, float* srstd)
{
    __syncthreads();
    int t = threadIdx.x;
    float s  = x0 + x1;
    float ss = x0 * x0 + x1 * x1;
    #pragma unroll
    for (int o = 16; o; o >>= 1) {
        s  += __shfl_xor_sync(0xffffffffu, s, o);
        ss += __shfl_xor_sync(0xffffffffu, ss, o);
    }
    int w = t >> 5, lane = t & 31;
    if (lane == 0) { shs[w] = s; shss[w] = ss; }
    __syncthreads();
    if (t == 0) {
        float a = 0.f, c = 0.f;
        #pragma unroll
        for (int i = 0; i < 8; ++i) { a += shs[i]; c += shss[i]; }
        float mu  = a * (1.0f / D_MODEL);
        float var = c * (1.0f / D_MODEL) - mu * mu;
        *smu = mu;
        *srstd = rsqrtf(var + LN_EPS);
    }
    __syncthreads();
    return make_float2(*smu, *srstd);
}

// ---------------------------------------------------------------- LayerNorm
__global__ void __launch_bounds__(256) ln_kernel(
    const float* __restrict__ in, const float* __restrict__ gamma,
    const float* __restrict__ beta, float* __restrict__ out,
    __half* __restrict__ outH)
{
    __shared__ float shs[8], shss[8], smu, srstd;
    int r = blockIdx.x;
    int t = threadIdx.x;
    const float* row = in + (size_t)r * D_MODEL;
    float x0 = row[t], x1 = row[t + 256];
    float2 mv = block_meanvar(x0, x1, shs, shss, &smu, &srstd);
    float y0 = (x0 - mv.x) * mv.y * gamma[t]       + beta[t];
    float y1 = (x1 - mv.x) * mv.y * gamma[t + 256] + beta[t + 256];
    size_t o0 = (size_t)r * D_MODEL + t;
    if (out) { out[o0] = y0; out[o0 + 256] = y1; }
    outH[o0]       = __float2half_rn(y0);
    outH[o0 + 256] = __float2half_rn(y1);
}

// Fused: t = LN2(inA + inB0 + inB1 + inB2); optional write; hn = LN_in(t).
__global__ void __launch_bounds__(256) ln2_lnin_kernel(
    const float* __restrict__ inA, const float* __restrict__ inB,
    const float* __restrict__ g2, const float* __restrict__ b2,
    float* __restrict__ outT,
    const float* __restrict__ gi, const float* __restrict__ bi,
    float* __restrict__ hn, __half* __restrict__ hnH)
{
    __shared__ float shs[8], shss[8], smu, srstd;
    int r = blockIdx.x;
    int t = threadIdx.x;
    size_t o0 = (size_t)r * D_MODEL + t;
    const size_t PS = (size_t)S_PAD * D_MODEL;
    float x0 = inA[o0]       + inB[o0]       + inB[o0 + PS]       + inB[o0 + 2 * PS];
    float x1 = inA[o0 + 256] + inB[o0 + 256] + inB[o0 + PS + 256] + inB[o0 + 2 * PS + 256];
    float2 mv = block_meanvar(x0, x1, shs, shss, &smu, &srstd);
    float t0 = (x0 - mv.x) * mv.y * g2[t]       + b2[t];
    float t1 = (x1 - mv.x) * mv.y * g2[t + 256] + b2[t + 256];
    if (outT) { outT[o0] = t0; outT[o0 + 256] = t1; }
    if (gi) {
        float2 mv2 = block_meanvar(t0, t1, shs, shss, &smu, &srstd);
        float u0 = (t0 - mv2.x) * mv2.y * gi[t]       + bi[t];
        float u1 = (t1 - mv2.x) * mv2.y * gi[t + 256] + bi[t + 256];
        hn[o0] = u0; hn[o0 + 256] = u1;
        hnH[o0]       = __float2half_rn(u0);
        hnH[o0 + 256] = __float2half_rn(u1);
    }
}

// ------------------------------------- single-launch weight prep (all layers)
__device__ __forceinline__ void tile64_transpose_split(
    const float* __restrict__ src, __half* __restrict__ dhi,
    __half* __restrict__ dlo, int K, int N, int n0, int k0, int tid)
{
    __shared__ float t[64][66];
    int tx = tid & 31, ty = tid >> 5;
    #pragma unroll
    for (int kk = ty; kk < 64; kk += 8) {
        float2 v = *reinterpret_cast<const float2*>(
            src + (size_t)(k0 + kk) * N + n0 + 2 * tx);
        t[2 * tx][kk]     = v.x;
        t[2 * tx + 1][kk] = v.y;
    }
    __syncthreads();
    #pragma unroll
    for (int it = 0; it < 8; ++it) {
        int nn = it * 8 + ty;
        float2 v = *reinterpret_cast<const float2*>(&t[nn][2 * tx]);
        __half h0 = __float2half_rn(v.x);
        __half h1 = __float2half_rn(v.y);
        __half2 hh; hh.x = h0; hh.y = h1;
        __half2 ll;
        ll.x = __float2half_rn((v.x - __half2float(h0)) * LO_SCALE);
        ll.y = __float2half_rn((v.y - __half2float(h1)) * LO_SCALE);
        size_t o = (size_t)(n0 + nn) * K + k0 + 2 * tx;
        *reinterpret_cast<__half2*>(dhi + o) = hh;
        *reinterpret_cast<__half2*>(dlo + o) = ll;
    }
}

#define PREP_PER_LAYER 704
#define PREP_TRANS_BLOCKS (PREP_PER_LAYER * NLAYERS)
#define PREP_BIAS_BLOCKS 48
#define PREP_BLOCKS (PREP_TRANS_BLOCKS + PREP_BIAS_BLOCKS)

__global__ void __launch_bounds__(256) prep_all(
    const float* __restrict__ wq, const float* __restrict__ wk,
    const float* __restrict__ wv, const float* __restrict__ w1,
    const float* __restrict__ w2,
    const float* __restrict__ bq, const float* __restrict__ bk,
    const float* __restrict__ bv,
    __half* __restrict__ wqkv_hi, __half* __restrict__ wqkv_lo,
    __half* __restrict__ w1t_hi,  __half* __restrict__ w1t_lo,
    __half* __restrict__ w2t_hi,  __half* __restrict__ w2t_lo,
    float* __restrict__ bqkv)
{
    int id = blockIdx.x;
    int tid = threadIdx.x;
    if (id >= PREP_TRANS_BLOCKS) {
        int i = (id - PREP_TRANS_BLOCKS) * 256 + tid;
        int l = i / QKV_N, c = i % QKV_N;
        float v;
        if (c < 512)       v = bq[l * 512 + c];
        else if (c < 1024) v = bk[l * 512 + c - 512];
        else               v = bv[l * 512 + c - 1024];
        bqkv[i] = v;
        return;
    }
    int l = id / PREP_PER_LAYER;
    int r = id % PREP_PER_LAYER;
    if (r < 192) {
        int which = r >> 6;
        int t = r & 63;
        const float* src = (which == 0) ? wq : (which == 1) ? wk : wv;
        src += (size_t)l * 512 * 512;
        size_t doff = (size_t)l * QKV_N * 512 + (size_t)which * 512 * 512;
        tile64_transpose_split(src, wqkv_hi + doff, wqkv_lo + doff,
                               512, 512, (t & 7) * 64, (t >> 3) * 64, tid);
    } else if (r < 448) {
        int t = r - 192;
        const float* src = w1 + (size_t)l * 512 * 2048;
        size_t doff = (size_t)l * FF_DIM * 512;
        tile64_transpose_split(src, w1t_hi + doff, w1t_lo + doff,
                               512, 2048, (t & 31) * 64, (t >> 5) * 64, tid);
    } else {
        int t = r - 448;
        const float* src = w2 + (size_t)l * 2048 * 512;
        size_t doff = (size_t)l * D_MODEL * FF_DIM;
        tile64_transpose_split(src, w2t_hi + doff, w2t_lo + doff,
                               2048, 512, (t & 7) * 64, (t >> 3) * 64, tid);
    }
}

// ------------------------------------------------------------- mma.sync GEMM
// fp16 2-pass: C = A*Bhi + 2^-11 * (A*Blo_scaled). BM=128, BN=64, BK=32,
// 4-stage cp.async, 8 warps (4x2), dual fp32 accumulators.
#define A_OFF   0
#define BHI_OFF 8192
#define BLO_OFF 12288
#define STAGE_BYTES 16384
#define GEMM_SMEM (4 * STAGE_BYTES)

__device__ __forceinline__ uint32_t phys(int r, int c) {
    return (uint32_t)(r * 64 + ((c ^ (r & 3)) << 4));
}

__global__ void __launch_bounds__(256, 2) gemm_tc(
    const __half* __restrict__ A,
    const __half* __restrict__ Bhi, const __half* __restrict__ Blo,
    const float* __restrict__ bias, const float* __restrict__ res,
    float* __restrict__ outF, float* __restrict__ outF2,
    __half* __restrict__ outH, int Klen, int ldK, int N)
{
    extern __shared__ char smraw[];
    const uint32_t sb = smem_u32(smraw);

    const int tid  = threadIdx.x;
    const int lane = tid & 31;
    const int wid  = tid >> 5;
    const int wm   = wid >> 1;
    const int wn   = wid & 1;
    const int m0   = blockIdx.x * 128;
    const int n0   = blockIdx.y * 64;
    const int kz   = blockIdx.z;
    const int koff = kz * Klen;

    const __half* a0 = A   + (size_t)m0 * ldK + koff;
    const __half* b0 = Bhi + (size_t)n0 * ldK + koff;
    const __half* b1 = Blo + (size_t)n0 * ldK + koff;

    const int r0c = tid >> 2, cc = tid & 3;
    const int r1c = r0c + 64;
    const uint32_t s0 = phys(r0c, cc), s1 = phys(r1c, cc);

    float acc[2][4][4], accL[2][4][4];
    #pragma unroll
    for (int i = 0; i < 2; ++i)
        #pragma unroll
        for (int j = 0; j < 4; ++j)
            #pragma unroll
            for (int k = 0; k < 4; ++k) { acc[i][j][k] = 0.f; accL[i][j][k] = 0.f; }

    const int NC = Klen >> 5;

    auto issue = [&](int c) {
        const uint32_t st = sb + (uint32_t)(c & 3) * STAGE_BYTES;
        const int k0 = c << 5;
        const size_t go0 = (size_t)r0c * ldK + k0 + cc * 8;
        const size_t go1 = (size_t)r1c * ldK + k0 + cc * 8;
        CP16(st + A_OFF + s0,   a0 + go0);
        CP16(st + A_OFF + s1,   a0 + go1);
        CP16(st + BHI_OFF + s0, b0 + go0);
        CP16(st + BLO_OFF + s0, b1 + go0);
    };

    issue(0); CP_COMMIT();
    issue(1); CP_COMMIT();
    issue(2); CP_COMMIT();

    const int lr = lane & 15, lc = lane >> 4;
    const int bg = lane >> 3, bi = lane & 7;
    const int arow0 = wm * 32 + lr;
    const int arow1 = arow0 + 16;
    const int browb = wn * 32 + ((bg >> 1) << 3) + bi;

    for (int c = 0; c < NC; ++c) {
        CP_WAIT2();
        __syncthreads();

        const uint32_t st = sb + (uint32_t)(c & 3) * STAGE_BYTES;
        #pragma unroll
        for (int ks = 0; ks < 2; ++ks) {
            const int ca = ks * 2 + lc;
            const int cb = ks * 2 + (bg & 1);
            uint32_t a0f[4], a1f[4];
            uint32_t bh[4], bh2[4], bl[4], bl2[4];
            LDSM4(a0f[0], a0f[1], a0f[2], a0f[3], st + A_OFF + phys(arow0, ca));
            LDSM4(a1f[0], a1f[1], a1f[2], a1f[3], st + A_OFF + phys(arow1, ca));
            LDSM4(bh[0], bh[1], bh[2], bh[3],     st + BHI_OFF + phys(browb, cb));
            LDSM4(bh2[0], bh2[1], bh2[2], bh2[3], st + BHI_OFF + phys(browb + 16, cb));
            LDSM4(bl[0], bl[1], bl[2], bl[3],     st + BLO_OFF + phys(browb, cb));
            LDSM4(bl2[0], bl2[1], bl2[2], bl2[3], st + BLO_OFF + phys(browb + 16, cb));

            MMA16816(acc[0][0], a0f, bh[0],  bh[1]);
            MMA16816(acc[0][1], a0f, bh[2],  bh[3]);
            MMA16816(acc[0][2], a0f, bh2[0], bh2[1]);
            MMA16816(acc[0][3], a0f, bh2[2], bh2[3]);
            MMA16816(acc[1][0], a1f, bh[0],  bh[1]);
            MMA16816(acc[1][1], a1f, bh[2],  bh[3]);
            MMA16816(acc[1][2], a1f, bh2[0], bh2[1]);
            MMA16816(acc[1][3], a1f, bh2[2], bh2[3]);

            MMA16816(accL[0][0], a0f, bl[0],  bl[1]);
            MMA16816(accL[0][1], a0f, bl[2],  bl[3]);
            MMA16816(accL[0][2], a0f, bl2[0], bl2[1]);
            MMA16816(accL[0][3], a0f, bl2[2], bl2[3]);
            MMA16816(accL[1][0], a1f, bl[0],  bl[1]);
            MMA16816(accL[1][1], a1f, bl[2],  bl[3]);
            MMA16816(accL[1][2], a1f, bl2[0], bl2[1]);
            MMA16816(accL[1][3], a1f, bl2[2], bl2[3]);
        }
        if (c + 3 < NC) issue(c + 3);
        CP_COMMIT();
    }

    // ------------------------------------------------------------- epilogue
    const int erow = (lane >> 2);
    const int ecol = (lane & 3) * 2;
    #pragma unroll
    for (int mt = 0; mt < 2; ++mt) {
        #pragma unroll
        for (int half = 0; half < 2; ++half) {
            const int row = m0 + wm * 32 + mt * 16 + erow + half * 8;
            #pragma unroll
            for (int nt = 0; nt < 4; ++nt) {
                const int col = n0 + wn * 32 + nt * 8 + ecol;
                float v0 = acc[mt][nt][half * 2 + 0] + accL[mt][nt][half * 2 + 0] * LO_INV;
                float v1 = acc[mt][nt][half * 2 + 1] + accL[mt][nt][half * 2 + 1] * LO_INV;
                if (kz >= 1) {
                    *reinterpret_cast<float2*>(
                        outF2 + (size_t)(kz - 1) * S_PAD * D_MODEL +
                        (size_t)row * N + col) = make_float2(v0, v1);
                    continue;
                }
                v0 += __ldg(bias + col);
                v1 += __ldg(bias + col + 1);
                if (res) {
                    const float2 r2 = *reinterpret_cast<const float2*>(
                        res + (size_t)row * N + col);
                    v0 += r2.x; v1 += r2.y;
                }
                if (outF)
                    *reinterpret_cast<float2*>(outF + (size_t)row * N + col) =
                        make_float2(v0, v1);
                if (outH) {
                    __half2 hh;
                    hh.x = __float2half_rn(v0);
                    hh.y = __float2half_rn(v1);
                    *reinterpret_cast<__half2*>(outH + (size_t)row * N + col) = hh;
                }
            }
        }
    }
}

// ---------------------------------------------- chunked sparse attention v5
// grid (32, 8), 512 threads. Key-major K (same layout as V), float4 staging
// and float4 score loop: 4x fewer LDS issues than v3 at identical bytes.
// Each warp register-blocks its <=3 queries across one d-sweep and one
// key-sweep (v3 schedule).
#define ATTN_THREADS 512

__global__ void __launch_bounds__(ATTN_THREADS) attn_chunk_kernel(
    const float* __restrict__ QKV, const float* __restrict__ QKV2,
    const float* __restrict__ hn, float* __restrict__ attnOut)
{
    __shared__ float Ks[64][68];   // [key][dim], rows nk..63 zero-filled
    __shared__ float Vs[60][68];   // [key][dim]
    __shared__ float Qs[40][68];   // [query][dim]

    const int i    = blockIdx.x;
    const int h    = blockIdx.y;
    const int tid  = threadIdx.x;
    const int w    = tid >> 5;
    const int lane = tid & 31;
    const int hoff = h * 64;

    const int bodyLo = max(0, 32 * i - 20);
    const int nb     = 32 * (i + 1) - bodyLo;
    const int nrc    = (i < 31) ? 8 : 0;
    const int nk     = nrc + nb;
    const int nq     = 32 + nrc;

    // stage K and V row-major via float4 (summing split-K halves)
    for (int e = tid; e < nk * 16; e += ATTN_THREADS) {
        int j = e >> 4, d = (e & 15) << 2;
        int kg = (j < nrc) ? (8 * i + j) : (UB + bodyLo + (j - nrc));
        size_t base = (size_t)kg * QKV_N + hoff + d;
        float4 k0 = *reinterpret_cast<const float4*>(QKV  + base + 512);
        float4 k1 = *reinterpret_cast<const float4*>(QKV2 + base + 512);
        float4 v0 = *reinterpret_cast<const float4*>(QKV  + base + 1024);
        float4 v1 = *reinterpret_cast<const float4*>(QKV2 + base + 1024);
        *reinterpret_cast<float4*>(&Ks[j][d]) =
            make_float4(k0.x + k1.x, k0.y + k1.y, k0.z + k1.z, k0.w + k1.w);
        *reinterpret_cast<float4*>(&Vs[j][d]) =
            make_float4(v0.x + v1.x, v0.y + v1.y, v0.z + v1.z, v0.w + v1.w);
    }
    // zero-fill K rows [nk, 64) so the lane+32 reads are defined
    for (int e = tid + nk * 16; e < 64 * 16; e += ATTN_THREADS) {
        int j = e >> 4, d = (e & 15) << 2;
        *reinterpret_cast<float4*>(&Ks[j][d]) = make_float4(0.f, 0.f, 0.f, 0.f);
    }
    // stage Q via float4 (scale folded, summing split-K halves)
    for (int e = tid; e < nq * 16; e += ATTN_THREADS) {
        int qq = e >> 4, d = (e & 15) << 2;
        int row = (qq < nrc) ? (8 * i + qq) : (UB + 32 * i + (qq - nrc));
        size_t base = (size_t)row * QKV_N + hoff + d;
        float4 q0 = *reinterpret_cast<const float4*>(QKV  + base);
        float4 q1 = *reinterpret_cast<const float4*>(QKV2 + base);
        *reinterpret_cast<float4*>(&Qs[qq][d]) =
            make_float4((q0.x + q1.x) * 0.125f, (q0.y + q1.y) * 0.125f,
                        (q0.z + q1.z) * 0.125f, (q0.w + q1.w) * 0.125f);
    }
    __syncthreads();

    const int lim1 = nk - 32;
    const int nqw = (nq - w + 15) >> 4;     // <= 3 queries: w, w+16, w+32

    // ---- scores: one d-sweep, float4 K loads shared across queries
    float s0[3] = {0.f, 0.f, 0.f}, s1[3] = {0.f, 0.f, 0.f};
    #pragma unroll 4
    for (int d = 0; d < 64; d += 4) {
        float4 k0 = *reinterpret_cast<const float4*>(&Ks[lane][d]);
        float4 k1 = *reinterpret_cast<const float4*>(&Ks[lane + 32][d]);
        #pragma unroll
        for (int t = 0; t < 3; ++t) {
            if (t < nqw) {
                float4 q = *reinterpret_cast<const float4*>(&Qs[w + 16 * t][d]);
                s0[t] = fmaf(q.x, k0.x, s0[t]);
                s0[t] = fmaf(q.y, k0.y, s0[t]);
                s0[t] = fmaf(q.z, k0.z, s0[t]);
                s0[t] = fmaf(q.w, k0.w, s0[t]);
                s1[t] = fmaf(q.x, k1.x, s1[t]);
                s1[t] = fmaf(q.y, k1.y, s1[t]);
                s1[t] = fmaf(q.z, k1.z, s1[t]);
                s1[t] = fmaf(q.w, k1.w, s1[t]);
            }
        }
    }

    // ---- per-query softmax
    float e0[3], e1[3], inv[3];
    #pragma unroll
    for (int t = 0; t < 3; ++t) {
        if (t >= nqw) { e0[t] = 0.f; e1[t] = 0.f; inv[t] = 0.f; continue; }
        float a0 = s0[t];
        float a1 = (lane < lim1) ? s1[t] : -1e30f;
        float m = fmaxf(a0, a1);
        #pragma unroll
        for (int o = 16; o; o >>= 1) m = fmaxf(m, __shfl_xor_sync(0xffffffffu, m, o));
        e0[t] = __expf(a0 - m);
        e1[t] = (lane < lim1) ? __expf(a1 - m) : 0.f;
        float ssum = e0[t] + e1[t];
        #pragma unroll
        for (int o = 16; o; o >>= 1) ssum += __shfl_xor_sync(0xffffffffu, ssum, o);
        inv[t] = 1.0f / ssum;
    }

    // ---- PV: one key-sweep, V loads shared across queries
    float o0[3] = {0.f, 0.f, 0.f}, o1[3] = {0.f, 0.f, 0.f};
    #pragma unroll 4
    for (int jj = 0; jj < 32; ++jj) {
        float2 v = *reinterpret_cast<const float2*>(&Vs[jj][2 * lane]);
        #pragma unroll
        for (int t = 0; t < 3; ++t) {
            float p = __shfl_sync(0xffffffffu, e0[t], jj);
            o0[t] = fmaf(p, v.x, o0[t]);
            o1[t] = fmaf(p, v.y, o1[t]);
        }
    }
    for (int jj = 0; jj < lim1; ++jj) {
        float2 v = *reinterpret_cast<const float2*>(&Vs[jj + 32][2 * lane]);
        #pragma unroll
        for (int t = 0; t < 3; ++t) {
            float p = __shfl_sync(0xffffffffu, e1[t], jj);
            o0[t] = fmaf(p, v.x, o0[t]);
            o1[t] = fmaf(p, v.y, o1[t]);
        }
    }

    // ---- write
    #pragma unroll
    for (int t = 0; t < 3; ++t) {
        if (t >= nqw) continue;
        const int qq = w + 16 * t;
        const int row = (qq < nrc) ? (8 * i + qq) : (UB + 32 * i + (qq - nrc));
        const size_t off = (size_t)row * D_MODEL + hoff + 2 * lane;
        const float2 hv = *reinterpret_cast<const float2*>(hn + off);
        *reinterpret_cast<float2*>(attnOut + off) =
            make_float2(o0[t] * inv[t] + hv.x, o1[t] * inv[t] + hv.y);
    }
}

// ------------------------------------------------------------------- driver
extern "C" void kernel_launch(void* const* d_in, const int* in_sizes, int n_in,
                              void* d_out, int out_size)
{
    (void)in_sizes; (void)n_in; (void)out_size;

    const float* x      = (const float*)d_in[0];
    const float* lnin_s = (const float*)d_in[2];
    const float* lnin_b = (const float*)d_in[3];
    const float* wq     = (const float*)d_in[4];
    const float* bq     = (const float*)d_in[5];
    const float* wk     = (const float*)d_in[6];
    const float* bk     = (const float*)d_in[7];
    const float* wv     = (const float*)d_in[8];
    const float* bv     = (const float*)d_in[9];
    const float* ln1_s  = (const float*)d_in[10];
    const float* ln1_b  = (const float*)d_in[11];
    const float* w1     = (const float*)d_in[12];
    const float* b1     = (const float*)d_in[13];
    const float* w2     = (const float*)d_in[14];
    const float* b2     = (const float*)d_in[15];
    const float* ln2_s  = (const float*)d_in[16];
    const float* ln2_b  = (const float*)d_in[17];
    float* out = (float*)d_out;

    float *p_hn, *p_attn, *p_ff2a, *p_ff2b, *p_qkv, *p_bqkv;
    __half *p_hn_h, *p_y_h, *p_ff_h;
    __half *p_wqkv_hi, *p_wqkv_lo, *p_w1t_hi, *p_w1t_lo, *p_w2t_hi, *p_w2t_lo;
    cudaGetSymbolAddress((void**)&p_hn,    g_hn);
    cudaGetSymbolAddress((void**)&p_attn,  g_attn);
    cudaGetSymbolAddress((void**)&p_ff2a,  g_ff2a);
    cudaGetSymbolAddress((void**)&p_ff2b,  g_ff2b);
    cudaGetSymbolAddress((void**)&p_qkv,   g_qkv);
    cudaGetSymbolAddress((void**)&p_bqkv,  g_bqkv);
    cudaGetSymbolAddress((void**)&p_hn_h,  g_hn_h);
    cudaGetSymbolAddress((void**)&p_y_h,   g_y_h);
    cudaGetSymbolAddress((void**)&p_ff_h,  g_ff_h);
    cudaGetSymbolAddress((void**)&p_wqkv_hi, g_wqkv_hi);
    cudaGetSymbolAddress((void**)&p_wqkv_lo, g_wqkv_lo);
    cudaGetSymbolAddress((void**)&p_w1t_hi,  g_w1t_hi);
    cudaGetSymbolAddress((void**)&p_w1t_lo,  g_w1t_lo);
    cudaGetSymbolAddress((void**)&p_w2t_hi,  g_w2t_hi);
    cudaGetSymbolAddress((void**)&p_w2t_lo,  g_w2t_lo);

    cudaFuncSetAttribute(gemm_tc, cudaFuncAttributeMaxDynamicSharedMemorySize,
                         GEMM_SMEM);

    dim3 blk(256);
    prep_all<<<PREP_BLOCKS, blk>>>(wq, wk, wv, w1, w2, bq, bk, bv,
                                   p_wqkv_hi, p_wqkv_lo, p_w1t_hi, p_w1t_lo,
                                   p_w2t_hi, p_w2t_lo, p_bqkv);

    const int MT = S_PAD / 128;   // 10
    for (int l = 0; l < NLAYERS; ++l) {
        size_t oD = (size_t)l * D_MODEL;
        size_t oF = (size_t)l * FF_DIM;

        if (l == 0)
            ln_kernel<<<S_LEN, blk>>>(x, lnin_s, lnin_b, p_hn, p_hn_h);

        // fused QKV split-K=2: BN=64, grid 10x24x2 = 480
        gemm_tc<<<dim3(MT, QKV_N / 64, 2), blk, GEMM_SMEM>>>(
            p_hn_h,
            p_wqkv_hi + (size_t)l * QKV_N * 512, p_wqkv_lo + (size_t)l * QKV_N * 512,
            p_bqkv + (size_t)l * QKV_N, nullptr,
            p_qkv, p_ff2b, nullptr, 256, 512, QKV_N);
        // chunked sparse attention v5 (+ residual onto hn)
        attn_chunk_kernel<<<dim3(32, 8), ATTN_THREADS>>>(p_qkv, p_ff2b,
                                                         p_hn, p_attn);
        // ln1 -> y fp16
        ln_kernel<<<S_LEN, blk>>>(p_attn, ln1_s + oD, ln1_b + oD,
                                  nullptr, p_y_h);
        // FFN1: BN=64, full K, grid 10x32 = 320
        gemm_tc<<<dim3(MT, FF_DIM / 64), blk, GEMM_SMEM>>>(
            p_y_h,
            p_w1t_hi + (size_t)l * FF_DIM * 512, p_w1t_lo + (size_t)l * FF_DIM * 512,
            b1 + oF, nullptr,
            nullptr, nullptr, p_ff_h, 512, 512, FF_DIM);
        // FFN2: BN=64, split-K=4, grid 10x8x4 = 320
        gemm_tc<<<dim3(MT, D_MODEL / 64, 4), blk, GEMM_SMEM>>>(
            p_ff_h,
            p_w2t_hi + (size_t)l * D_MODEL * FF_DIM, p_w2t_lo + (size_t)l * D_MODEL * FF_DIM,
            b2 + oD, p_attn,
            p_ff2a, p_ff2b, nullptr, 512, FF_DIM, D_MODEL);
        if (l < NLAYERS - 1) {
            ln2_lnin_kernel<<<S_LEN, blk>>>(
                p_ff2a, p_ff2b, ln2_s + oD, ln2_b + oD, nullptr,
                lnin_s + oD + D_MODEL, lnin_b + oD + D_MODEL,
                p_hn, p_hn_h);
        } else {
            ln2_lnin_kernel<<<S_LEN, blk>>>(
                p_ff2a, p_ff2b, ln2_s + oD, ln2_b + oD, out,
                nullptr, nullptr, nullptr, nullptr);
        }
    }
}

// round 15
// speedup vs baseline: 1.0970x; 1.0195x over previous
#include <cuda_runtime.h>
#include <cuda_fp16.h>
#include <stdint.h>
#include <math.h>

// ---------------------------------------------------------------- constants
#define S_LEN   1272
#define S_PAD   1280
#define D_MODEL 512
#define QKV_N   1536
#define FF_DIM  2048
#define NLAYERS 8
#define UB      248
#define LN_EPS  1e-3f
#define LO_SCALE    2048.0f
#define LO_INV      4.8828125e-4f   // 1/2048

// ---------------------------------------------------------------- scratch
__device__ float g_hn  [S_PAD * D_MODEL];
__device__ float g_attn[S_PAD * D_MODEL];
__device__ float g_ff2a[S_PAD * D_MODEL];
__device__ float g_ff2b[3 * S_PAD * D_MODEL];   // FFN2 split-K partials
__device__ float g_qkv [S_PAD * QKV_N];
__device__ float g_bqkv[NLAYERS * QKV_N];

__device__ __half g_hn_h[S_PAD * D_MODEL];
__device__ __half g_y_h [S_PAD * D_MODEL];
__device__ __half g_ff_h[S_PAD * FF_DIM];

__device__ __half g_wqkv_hi[NLAYERS * QKV_N * D_MODEL];
__device__ __half g_wqkv_lo[NLAYERS * QKV_N * D_MODEL];   // scaled by 2^11
__device__ __half g_w1t_hi [NLAYERS * FF_DIM * D_MODEL];
__device__ __half g_w1t_lo [NLAYERS * FF_DIM * D_MODEL];
__device__ __half g_w2t_hi [NLAYERS * D_MODEL * FF_DIM];
__device__ __half g_w2t_lo [NLAYERS * D_MODEL * FF_DIM];

// ---------------------------------------------------------------- PTX utils
__device__ __forceinline__ uint32_t smem_u32(const void* p) {
    uint32_t a;
    asm("{ .reg .u64 t; cvta.to.shared.u64 t, %1; cvt.u32.u64 %0, t; }"
        : "=r"(a) : "l"(p));
    return a;
}

#define CP16(s, g) \
    asm volatile("cp.async.cg.shared.global [%0], [%1], 16;" :: "r"(s), "l"(g))
#define CP_COMMIT() asm volatile("cp.async.commit_group;" ::: "memory")
#define CP_WAIT2()  asm volatile("cp.async.wait_group 2;" ::: "memory")

#define LDSM4(r0, r1, r2, r3, a) \
    asm volatile("ldmatrix.sync.aligned.m8n8.x4.shared.b16 {%0,%1,%2,%3}, [%4];" \
                 : "=r"(r0), "=r"(r1), "=r"(r2), "=r"(r3) : "r"(a))

#define MMA16816(c, a, b0, b1)                                                \
    asm volatile("mma.sync.aligned.m16n8k16.row.col.f32.f16.f16.f32 "         \
                 "{%0,%1,%2,%3}, {%4,%5,%6,%7}, {%8,%9}, {%0,%1,%2,%3};"      \
                 : "+f"((c)[0]), "+f"((c)[1]), "+f"((c)[2]), "+f"((c)[3])     \
                 : "r"((a)[0]), "r"((a)[1]), "r"((a)[2]), "r"((a)[3]),        \
                   "r"(b0), "r"(b1))

// ----------------------------------------------------------- block LN reduce
__device__ __forceinline__ float2 block_meanvar(float x0, float x1,
                                                float* shs, float* shss,
                                                float* smu, float* srstd)
{
    __syncthreads();
    int t = threadIdx.x;
    float s  = x0 + x1;
    float ss = x0 * x0 + x1 * x1;
    #pragma unroll
    for (int o = 16; o; o >>= 1) {
        s  += __shfl_xor_sync(0xffffffffu, s, o);
        ss += __shfl_xor_sync(0xffffffffu, ss, o);
    }
    int w = t >> 5, lane = t & 31;
    if (lane == 0) { shs[w] = s; shss[w] = ss; }
    __syncthreads();
    if (t == 0) {
        float a = 0.f, c = 0.f;
        #pragma unroll
        for (int i = 0; i < 8; ++i) { a += shs[i]; c += shss[i]; }
        float mu  = a * (1.0f / D_MODEL);
        float var = c * (1.0f / D_MODEL) - mu * mu;
        *smu = mu;
        *srstd = rsqrtf(var + LN_EPS);
    }
    __syncthreads();
    return make_float2(*smu, *srstd);
}

// ---------------------------------------------------------------- LayerNorm
__global__ void __launch_bounds__(256) ln_kernel(
    const float* __restrict__ in, const float* __restrict__ gamma,
    const float* __restrict__ beta, float* __restrict__ out,
    __half* __restrict__ outH)
{
    __shared__ float shs[8], shss[8], smu, srstd;
    int r = blockIdx.x;
    int t = threadIdx.x;
    const float* row = in + (size_t)r * D_MODEL;
    float x0 = row[t], x1 = row[t + 256];
    float2 mv = block_meanvar(x0, x1, shs, shss, &smu, &srstd);
    float y0 = (x0 - mv.x) * mv.y * gamma[t]       + beta[t];
    float y1 = (x1 - mv.x) * mv.y * gamma[t + 256] + beta[t + 256];
    size_t o0 = (size_t)r * D_MODEL + t;
    if (out) { out[o0] = y0; out[o0 + 256] = y1; }
    outH[o0]       = __float2half_rn(y0);
    outH[o0 + 256] = __float2half_rn(y1);
}

// Fused: t = LN2(inA + inB0 + inB1 + inB2); optional write; hn = LN_in(t).
__global__ void __launch_bounds__(256) ln2_lnin_kernel(
    const float* __restrict__ inA, const float* __restrict__ inB,
    const float* __restrict__ g2, const float* __restrict__ b2,
    float* __restrict__ outT,
    const float* __restrict__ gi, const float* __restrict__ bi,
    float* __restrict__ hn, __half* __restrict__ hnH)
{
    __shared__ float shs[8], shss[8], smu, srstd;
    int r = blockIdx.x;
    int t = threadIdx.x;
    size_t o0 = (size_t)r * D_MODEL + t;
    const size_t PS = (size_t)S_PAD * D_MODEL;
    float x0 = inA[o0]       + inB[o0]       + inB[o0 + PS]       + inB[o0 + 2 * PS];
    float x1 = inA[o0 + 256] + inB[o0 + 256] + inB[o0 + PS + 256] + inB[o0 + 2 * PS + 256];
    float2 mv = block_meanvar(x0, x1, shs, shss, &smu, &srstd);
    float t0 = (x0 - mv.x) * mv.y * g2[t]       + b2[t];
    float t1 = (x1 - mv.x) * mv.y * g2[t + 256] + b2[t + 256];
    if (outT) { outT[o0] = t0; outT[o0 + 256] = t1; }
    if (gi) {
        float2 mv2 = block_meanvar(t0, t1, shs, shss, &smu, &srstd);
        float u0 = (t0 - mv2.x) * mv2.y * gi[t]       + bi[t];
        float u1 = (t1 - mv2.x) * mv2.y * gi[t + 256] + bi[t + 256];
        hn[o0] = u0; hn[o0 + 256] = u1;
        hnH[o0]       = __float2half_rn(u0);
        hnH[o0 + 256] = __float2half_rn(u1);
    }
}

// ------------------------------------- single-launch weight prep (all layers)
__device__ __forceinline__ void tile64_transpose_split(
    const float* __restrict__ src, __half* __restrict__ dhi,
    __half* __restrict__ dlo, int K, int N, int n0, int k0, int tid)
{
    __shared__ float t[64][66];
    int tx = tid & 31, ty = tid >> 5;
    #pragma unroll
    for (int kk = ty; kk < 64; kk += 8) {
        float2 v = *reinterpret_cast<const float2*>(
            src + (size_t)(k0 + kk) * N + n0 + 2 * tx);
        t[2 * tx][kk]     = v.x;
        t[2 * tx + 1][kk] = v.y;
    }
    __syncthreads();
    #pragma unroll
    for (int it = 0; it < 8; ++it) {
        int nn = it * 8 + ty;
        float2 v = *reinterpret_cast<const float2*>(&t[nn][2 * tx]);
        __half h0 = __float2half_rn(v.x);
        __half h1 = __float2half_rn(v.y);
        __half2 hh; hh.x = h0; hh.y = h1;
        __half2 ll;
        ll.x = __float2half_rn((v.x - __half2float(h0)) * LO_SCALE);
        ll.y = __float2half_rn((v.y - __half2float(h1)) * LO_SCALE);
        size_t o = (size_t)(n0 + nn) * K + k0 + 2 * tx;
        *reinterpret_cast<__half2*>(dhi + o) = hh;
        *reinterpret_cast<__half2*>(dlo + o) = ll;
    }
}

#define PREP_PER_LAYER 704
#define PREP_TRANS_BLOCKS (PREP_PER_LAYER * NLAYERS)
#define PREP_BIAS_BLOCKS 48
#define PREP_BLOCKS (PREP_TRANS_BLOCKS + PREP_BIAS_BLOCKS)

__global__ void __launch_bounds__(256) prep_all(
    const float* __restrict__ wq, const float* __restrict__ wk,
    const float* __restrict__ wv, const float* __restrict__ w1,
    const float* __restrict__ w2,
    const float* __restrict__ bq, const float* __restrict__ bk,
    const float* __restrict__ bv,
    __half* __restrict__ wqkv_hi, __half* __restrict__ wqkv_lo,
    __half* __restrict__ w1t_hi,  __half* __restrict__ w1t_lo,
    __half* __restrict__ w2t_hi,  __half* __restrict__ w2t_lo,
    float* __restrict__ bqkv)
{
    int id = blockIdx.x;
    int tid = threadIdx.x;
    if (id >= PREP_TRANS_BLOCKS) {
        int i = (id - PREP_TRANS_BLOCKS) * 256 + tid;
        int l = i / QKV_N, c = i % QKV_N;
        float v;
        if (c < 512)       v = bq[l * 512 + c];
        else if (c < 1024) v = bk[l * 512 + c - 512];
        else               v = bv[l * 512 + c - 1024];
        bqkv[i] = v;
        return;
    }
    int l = id / PREP_PER_LAYER;
    int r = id % PREP_PER_LAYER;
    if (r < 192) {
        int which = r >> 6;
        int t = r & 63;
        const float* src = (which == 0) ? wq : (which == 1) ? wk : wv;
        src += (size_t)l * 512 * 512;
        size_t doff = (size_t)l * QKV_N * 512 + (size_t)which * 512 * 512;
        tile64_transpose_split(src, wqkv_hi + doff, wqkv_lo + doff,
                               512, 512, (t & 7) * 64, (t >> 3) * 64, tid);
    } else if (r < 448) {
        int t = r - 192;
        const float* src = w1 + (size_t)l * 512 * 2048;
        size_t doff = (size_t)l * FF_DIM * 512;
        tile64_transpose_split(src, w1t_hi + doff, w1t_lo + doff,
                               512, 2048, (t & 31) * 64, (t >> 5) * 64, tid);
    } else {
        int t = r - 448;
        const float* src = w2 + (size_t)l * 2048 * 512;
        size_t doff = (size_t)l * D_MODEL * FF_DIM;
        tile64_transpose_split(src, w2t_hi + doff, w2t_lo + doff,
                               2048, 512, (t & 7) * 64, (t >> 3) * 64, tid);
    }
}

// ------------------------------------------------------------- mma.sync GEMM
// fp16 2-pass: C = A*Bhi + 2^-11 * (A*Blo_scaled). BM=128, BN=64, BK=32,
// 4-stage cp.async, 8 warps (4x2), dual fp32 accumulators.
#define A_OFF   0
#define BHI_OFF 8192
#define BLO_OFF 12288
#define STAGE_BYTES 16384
#define GEMM_SMEM (4 * STAGE_BYTES)

__device__ __forceinline__ uint32_t phys(int r, int c) {
    return (uint32_t)(r * 64 + ((c ^ (r & 3)) << 4));
}

__global__ void __launch_bounds__(256, 2) gemm_tc(
    const __half* __restrict__ A,
    const __half* __restrict__ Bhi, const __half* __restrict__ Blo,
    const float* __restrict__ bias, const float* __restrict__ res,
    float* __restrict__ outF, float* __restrict__ outF2,
    __half* __restrict__ outH, int Klen, int ldK, int N)
{
    extern __shared__ char smraw[];
    const uint32_t sb = smem_u32(smraw);

    const int tid  = threadIdx.x;
    const int lane = tid & 31;
    const int wid  = tid >> 5;
    const int wm   = wid >> 1;
    const int wn   = wid & 1;
    const int m0   = blockIdx.x * 128;
    const int n0   = blockIdx.y * 64;
    const int kz   = blockIdx.z;
    const int koff = kz * Klen;

    const __half* a0 = A   + (size_t)m0 * ldK + koff;
    const __half* b0 = Bhi + (size_t)n0 * ldK + koff;
    const __half* b1 = Blo + (size_t)n0 * ldK + koff;

    const int r0c = tid >> 2, cc = tid & 3;
    const int r1c = r0c + 64;
    const uint32_t s0 = phys(r0c, cc), s1 = phys(r1c, cc);

    float acc[2][4][4], accL[2][4][4];
    #pragma unroll
    for (int i = 0; i < 2; ++i)
        #pragma unroll
        for (int j = 0; j < 4; ++j)
            #pragma unroll
            for (int k = 0; k < 4; ++k) { acc[i][j][k] = 0.f; accL[i][j][k] = 0.f; }

    const int NC = Klen >> 5;

    auto issue = [&](int c) {
        const uint32_t st = sb + (uint32_t)(c & 3) * STAGE_BYTES;
        const int k0 = c << 5;
        const size_t go0 = (size_t)r0c * ldK + k0 + cc * 8;
        const size_t go1 = (size_t)r1c * ldK + k0 + cc * 8;
        CP16(st + A_OFF + s0,   a0 + go0);
        CP16(st + A_OFF + s1,   a0 + go1);
        CP16(st + BHI_OFF + s0, b0 + go0);
        CP16(st + BLO_OFF + s0, b1 + go0);
    };

    issue(0); CP_COMMIT();
    issue(1); CP_COMMIT();
    issue(2); CP_COMMIT();

    const int lr = lane & 15, lc = lane >> 4;
    const int bg = lane >> 3, bi = lane & 7;
    const int arow0 = wm * 32 + lr;
    const int arow1 = arow0 + 16;
    const int browb = wn * 32 + ((bg >> 1) << 3) + bi;

    for (int c = 0; c < NC; ++c) {
        CP_WAIT2();
        __syncthreads();

        const uint32_t st = sb + (uint32_t)(c & 3) * STAGE_BYTES;
        #pragma unroll
        for (int ks = 0; ks < 2; ++ks) {
            const int ca = ks * 2 + lc;
            const int cb = ks * 2 + (bg & 1);
            uint32_t a0f[4], a1f[4];
            uint32_t bh[4], bh2[4], bl[4], bl2[4];
            LDSM4(a0f[0], a0f[1], a0f[2], a0f[3], st + A_OFF + phys(arow0, ca));
            LDSM4(a1f[0], a1f[1], a1f[2], a1f[3], st + A_OFF + phys(arow1, ca));
            LDSM4(bh[0], bh[1], bh[2], bh[3],     st + BHI_OFF + phys(browb, cb));
            LDSM4(bh2[0], bh2[1], bh2[2], bh2[3], st + BHI_OFF + phys(browb + 16, cb));
            LDSM4(bl[0], bl[1], bl[2], bl[3],     st + BLO_OFF + phys(browb, cb));
            LDSM4(bl2[0], bl2[1], bl2[2], bl2[3], st + BLO_OFF + phys(browb + 16, cb));

            MMA16816(acc[0][0], a0f, bh[0],  bh[1]);
            MMA16816(acc[0][1], a0f, bh[2],  bh[3]);
            MMA16816(acc[0][2], a0f, bh2[0], bh2[1]);
            MMA16816(acc[0][3], a0f, bh2[2], bh2[3]);
            MMA16816(acc[1][0], a1f, bh[0],  bh[1]);
            MMA16816(acc[1][1], a1f, bh[2],  bh[3]);
            MMA16816(acc[1][2], a1f, bh2[0], bh2[1]);
            MMA16816(acc[1][3], a1f, bh2[2], bh2[3]);

            MMA16816(accL[0][0], a0f, bl[0],  bl[1]);
            MMA16816(accL[0][1], a0f, bl[2],  bl[3]);
            MMA16816(accL[0][2], a0f, bl2[0], bl2[1]);
            MMA16816(accL[0][3], a0f, bl2[2], bl2[3]);
            MMA16816(accL[1][0], a1f, bl[0],  bl[1]);
            MMA16816(accL[1][1], a1f, bl[2],  bl[3]);
            MMA16816(accL[1][2], a1f, bl2[0], bl2[1]);
            MMA16816(accL[1][3], a1f, bl2[2], bl2[3]);
        }
        if (c + 3 < NC) issue(c + 3);
        CP_COMMIT();
    }

    // ------------------------------------------------------------- epilogue
    const int erow = (lane >> 2);
    const int ecol = (lane & 3) * 2;
    #pragma unroll
    for (int mt = 0; mt < 2; ++mt) {
        #pragma unroll
        for (int half = 0; half < 2; ++half) {
            const int row = m0 + wm * 32 + mt * 16 + erow + half * 8;
            #pragma unroll
            for (int nt = 0; nt < 4; ++nt) {
                const int col = n0 + wn * 32 + nt * 8 + ecol;
                float v0 = acc[mt][nt][half * 2 + 0] + accL[mt][nt][half * 2 + 0] * LO_INV;
                float v1 = acc[mt][nt][half * 2 + 1] + accL[mt][nt][half * 2 + 1] * LO_INV;
                if (kz >= 1) {
                    *reinterpret_cast<float2*>(
                        outF2 + (size_t)(kz - 1) * S_PAD * D_MODEL +
                        (size_t)row * N + col) = make_float2(v0, v1);
                    continue;
                }
                v0 += __ldg(bias + col);
                v1 += __ldg(bias + col + 1);
                if (res) {
                    const float2 r2 = *reinterpret_cast<const float2*>(
                        res + (size_t)row * N + col);
                    v0 += r2.x; v1 += r2.y;
                }
                if (outF)
                    *reinterpret_cast<float2*>(outF + (size_t)row * N + col) =
                        make_float2(v0, v1);
                if (outH) {
                    __half2 hh;
                    hh.x = __float2half_rn(v0);
                    hh.y = __float2half_rn(v1);
                    *reinterpret_cast<__half2*>(outH + (size_t)row * N + col) = hh;
                }
            }
        }
    }
}

// ---------------------------------------------- chunked sparse attention v6
// grid (32, 8), 512 threads. Single fp32 QKV buffer (no split-K partials).
// Key-major float4 staging and score loop (v5 structure).
#define ATTN_THREADS 512

__global__ void __launch_bounds__(ATTN_THREADS) attn_chunk_kernel(
    const float* __restrict__ QKV,
    const float* __restrict__ hn, float* __restrict__ attnOut)
{
    __shared__ float Ks[64][68];   // [key][dim], rows nk..63 zero-filled
    __shared__ float Vs[60][68];   // [key][dim]
    __shared__ float Qs[40][68];   // [query][dim]

    const int i    = blockIdx.x;
    const int h    = blockIdx.y;
    const int tid  = threadIdx.x;
    const int w    = tid >> 5;
    const int lane = tid & 31;
    const int hoff = h * 64;

    const int bodyLo = max(0, 32 * i - 20);
    const int nb     = 32 * (i + 1) - bodyLo;
    const int nrc    = (i < 31) ? 8 : 0;
    const int nk     = nrc + nb;
    const int nq     = 32 + nrc;

    // stage K and V row-major via float4
    for (int e = tid; e < nk * 16; e += ATTN_THREADS) {
        int j = e >> 4, d = (e & 15) << 2;
        int kg = (j < nrc) ? (8 * i + j) : (UB + bodyLo + (j - nrc));
        size_t base = (size_t)kg * QKV_N + hoff + d;
        *reinterpret_cast<float4*>(&Ks[j][d]) =
            *reinterpret_cast<const float4*>(QKV + base + 512);
        *reinterpret_cast<float4*>(&Vs[j][d]) =
            *reinterpret_cast<const float4*>(QKV + base + 1024);
    }
    // zero-fill K rows [nk, 64) so the lane+32 reads are defined
    for (int e = tid + nk * 16; e < 64 * 16; e += ATTN_THREADS) {
        int j = e >> 4, d = (e & 15) << 2;
        *reinterpret_cast<float4*>(&Ks[j][d]) = make_float4(0.f, 0.f, 0.f, 0.f);
    }
    // stage Q via float4 (scale folded)
    for (int e = tid; e < nq * 16; e += ATTN_THREADS) {
        int qq = e >> 4, d = (e & 15) << 2;
        int row = (qq < nrc) ? (8 * i + qq) : (UB + 32 * i + (qq - nrc));
        float4 q = *reinterpret_cast<const float4*>(
            QKV + (size_t)row * QKV_N + hoff + d);
        *reinterpret_cast<float4*>(&Qs[qq][d]) =
            make_float4(q.x * 0.125f, q.y * 0.125f, q.z * 0.125f, q.w * 0.125f);
    }
    __syncthreads();

    const int lim1 = nk - 32;
    const int nqw = (nq - w + 15) >> 4;     // <= 3 queries: w, w+16, w+32

    // ---- scores: one d-sweep, float4 K loads shared across queries
    float s0[3] = {0.f, 0.f, 0.f}, s1[3] = {0.f, 0.f, 0.f};
    #pragma unroll 4
    for (int d = 0; d < 64; d += 4) {
        float4 k0 = *reinterpret_cast<const float4*>(&Ks[lane][d]);
        float4 k1 = *reinterpret_cast<const float4*>(&Ks[lane + 32][d]);
        #pragma unroll
        for (int t = 0; t < 3; ++t) {
            if (t < nqw) {
                float4 q = *reinterpret_cast<const float4*>(&Qs[w + 16 * t][d]);
                s0[t] = fmaf(q.x, k0.x, s0[t]);
                s0[t] = fmaf(q.y, k0.y, s0[t]);
                s0[t] = fmaf(q.z, k0.z, s0[t]);
                s0[t] = fmaf(q.w, k0.w, s0[t]);
                s1[t] = fmaf(q.x, k1.x, s1[t]);
                s1[t] = fmaf(q.y, k1.y, s1[t]);
                s1[t] = fmaf(q.z, k1.z, s1[t]);
                s1[t] = fmaf(q.w, k1.w, s1[t]);
            }
        }
    }

    // ---- per-query softmax
    float e0[3], e1[3], inv[3];
    #pragma unroll
    for (int t = 0; t < 3; ++t) {
        if (t >= nqw) { e0[t] = 0.f; e1[t] = 0.f; inv[t] = 0.f; continue; }
        float a0 = s0[t];
        float a1 = (lane < lim1) ? s1[t] : -1e30f;
        float m = fmaxf(a0, a1);
        #pragma unroll
        for (int o = 16; o; o >>= 1) m = fmaxf(m, __shfl_xor_sync(0xffffffffu, m, o));
        e0[t] = __expf(a0 - m);
        e1[t] = (lane < lim1) ? __expf(a1 - m) : 0.f;
        float ssum = e0[t] + e1[t];
        #pragma unroll
        for (int o = 16; o; o >>= 1) ssum += __shfl_xor_sync(0xffffffffu, ssum, o);
        inv[t] = 1.0f / ssum;
    }

    // ---- PV: one key-sweep, V loads shared across queries
    float o0[3] = {0.f, 0.f, 0.f}, o1[3] = {0.f, 0.f, 0.f};
    #pragma unroll 4
    for (int jj = 0; jj < 32; ++jj) {
        float2 v = *reinterpret_cast<const float2*>(&Vs[jj][2 * lane]);
        #pragma unroll
        for (int t = 0; t < 3; ++t) {
            float p = __shfl_sync(0xffffffffu, e0[t], jj);
            o0[t] = fmaf(p, v.x, o0[t]);
            o1[t] = fmaf(p, v.y, o1[t]);
        }
    }
    for (int jj = 0; jj < lim1; ++jj) {
        float2 v = *reinterpret_cast<const float2*>(&Vs[jj + 32][2 * lane]);
        #pragma unroll
        for (int t = 0; t < 3; ++t) {
            float p = __shfl_sync(0xffffffffu, e1[t], jj);
            o0[t] = fmaf(p, v.x, o0[t]);
            o1[t] = fmaf(p, v.y, o1[t]);
        }
    }

    // ---- write
    #pragma unroll
    for (int t = 0; t < 3; ++t) {
        if (t >= nqw) continue;
        const int qq = w + 16 * t;
        const int row = (qq < nrc) ? (8 * i + qq) : (UB + 32 * i + (qq - nrc));
        const size_t off = (size_t)row * D_MODEL + hoff + 2 * lane;
        const float2 hv = *reinterpret_cast<const float2*>(hn + off);
        *reinterpret_cast<float2*>(attnOut + off) =
            make_float2(o0[t] * inv[t] + hv.x, o1[t] * inv[t] + hv.y);
    }
}

// ------------------------------------------------------------------- driver
extern "C" void kernel_launch(void* const* d_in, const int* in_sizes, int n_in,
                              void* d_out, int out_size)
{
    (void)in_sizes; (void)n_in; (void)out_size;

    const float* x      = (const float*)d_in[0];
    const float* lnin_s = (const float*)d_in[2];
    const float* lnin_b = (const float*)d_in[3];
    const float* wq     = (const float*)d_in[4];
    const float* bq     = (const float*)d_in[5];
    const float* wk     = (const float*)d_in[6];
    const float* bk     = (const float*)d_in[7];
    const float* wv     = (const float*)d_in[8];
    const float* bv     = (const float*)d_in[9];
    const float* ln1_s  = (const float*)d_in[10];
    const float* ln1_b  = (const float*)d_in[11];
    const float* w1     = (const float*)d_in[12];
    const float* b1     = (const float*)d_in[13];
    const float* w2     = (const float*)d_in[14];
    const float* b2     = (const float*)d_in[15];
    const float* ln2_s  = (const float*)d_in[16];
    const float* ln2_b  = (const float*)d_in[17];
    float* out = (float*)d_out;

    float *p_hn, *p_attn, *p_ff2a, *p_ff2b, *p_qkv, *p_bqkv;
    __half *p_hn_h, *p_y_h, *p_ff_h;
    __half *p_wqkv_hi, *p_wqkv_lo, *p_w1t_hi, *p_w1t_lo, *p_w2t_hi, *p_w2t_lo;
    cudaGetSymbolAddress((void**)&p_hn,    g_hn);
    cudaGetSymbolAddress((void**)&p_attn,  g_attn);
    cudaGetSymbolAddress((void**)&p_ff2a,  g_ff2a);
    cudaGetSymbolAddress((void**)&p_ff2b,  g_ff2b);
    cudaGetSymbolAddress((void**)&p_qkv,   g_qkv);
    cudaGetSymbolAddress((void**)&p_bqkv,  g_bqkv);
    cudaGetSymbolAddress((void**)&p_hn_h,  g_hn_h);
    cudaGetSymbolAddress((void**)&p_y_h,   g_y_h);
    cudaGetSymbolAddress((void**)&p_ff_h,  g_ff_h);
    cudaGetSymbolAddress((void**)&p_wqkv_hi, g_wqkv_hi);
    cudaGetSymbolAddress((void**)&p_wqkv_lo, g_wqkv_lo);
    cudaGetSymbolAddress((void**)&p_w1t_hi,  g_w1t_hi);
    cudaGetSymbolAddress((void**)&p_w1t_lo,  g_w1t_lo);
    cudaGetSymbolAddress((void**)&p_w2t_hi,  g_w2t_hi);
    cudaGetSymbolAddress((void**)&p_w2t_lo,  g_w2t_lo);

    cudaFuncSetAttribute(gemm_tc, cudaFuncAttributeMaxDynamicSharedMemorySize,
                         GEMM_SMEM);

    dim3 blk(256);
    prep_all<<<PREP_BLOCKS, blk>>>(wq, wk, wv, w1, w2, bq, bk, bv,
                                   p_wqkv_hi, p_wqkv_lo, p_w1t_hi, p_w1t_lo,
                                   p_w2t_hi, p_w2t_lo, p_bqkv);

    const int MT = S_PAD / 128;   // 10
    for (int l = 0; l < NLAYERS; ++l) {
        size_t oD = (size_t)l * D_MODEL;
        size_t oF = (size_t)l * FF_DIM;

        if (l == 0)
            ln_kernel<<<S_LEN, blk>>>(x, lnin_s, lnin_b, p_hn, p_hn_h);

        // fused QKV, full K (no split-K): BN=64, grid 10x24 = 240
        gemm_tc<<<dim3(MT, QKV_N / 64), blk, GEMM_SMEM>>>(
            p_hn_h,
            p_wqkv_hi + (size_t)l * QKV_N * 512, p_wqkv_lo + (size_t)l * QKV_N * 512,
            p_bqkv + (size_t)l * QKV_N, nullptr,
            p_qkv, nullptr, nullptr, 512, 512, QKV_N);
        // chunked sparse attention v6 (+ residual onto hn)
        attn_chunk_kernel<<<dim3(32, 8), ATTN_THREADS>>>(p_qkv, p_hn, p_attn);
        // ln1 -> y fp16
        ln_kernel<<<S_LEN, blk>>>(p_attn, ln1_s + oD, ln1_b + oD,
                                  nullptr, p_y_h);
        // FFN1: BN=64, full K, grid 10x32 = 320
        gemm_tc<<<dim3(MT, FF_DIM / 64), blk, GEMM_SMEM>>>(
            p_y_h,
            p_w1t_hi + (size_t)l * FF_DIM * 512, p_w1t_lo + (size_t)l * FF_DIM * 512,
            b1 + oF, nullptr,
            nullptr, nullptr, p_ff_h, 512, 512, FF_DIM);
        // FFN2: BN=64, split-K=4, grid 10x8x4 = 320
        gemm_tc<<<dim3(MT, D_MODEL / 64, 4), blk, GEMM_SMEM>>>(
            p_ff_h,
            p_w2t_hi + (size_t)l * D_MODEL * FF_DIM, p_w2t_lo + (size_t)l * D_MODEL * FF_DIM,
            b2 + oD, p_attn,
            p_ff2a, p_ff2b, nullptr, 512, FF_DIM, D_MODEL);
        if (l < NLAYERS - 1) {
            ln2_lnin_kernel<<<S_LEN, blk>>>(
                p_ff2a, p_ff2b, ln2_s + oD, ln2_b + oD, nullptr,
                lnin_s + oD + D_MODEL, lnin_b + oD + D_MODEL,
                p_hn, p_hn_h);
        } else {
            ln2_lnin_kernel<<<S_LEN, blk>>>(
                p_ff2a, p_ff2b, ln2_s + oD, ln2_b + oD, out,
                nullptr, nullptr, nullptr, nullptr);
        }
    }
}

// round 16
// speedup vs baseline: 1.3883x; 1.2655x over previous
#include <cuda_runtime.h>
#include <cuda_fp16.h>
#include <stdint.h>
#include <math.h>

// ---------------------------------------------------------------- constants
#define S_LEN   1272
#define S_PAD   1280
#define D_MODEL 512
#define QKV_N   1536
#define FF_DIM  2048
#define NLAYERS 8
#define UB      248
#define LN_EPS  1e-3f

// ---------------------------------------------------------------- scratch
__device__ float g_hn  [S_PAD * D_MODEL];
__device__ float g_attn[S_PAD * D_MODEL];
__device__ float g_ff2a[S_PAD * D_MODEL];
__device__ float g_ff2b[3 * S_PAD * D_MODEL];   // FFN2 split-K partials
__device__ float g_qkv [S_PAD * QKV_N];
__device__ float g_bqkv[NLAYERS * QKV_N];

__device__ __half g_hn_h[S_PAD * D_MODEL];
__device__ __half g_y_h [S_PAD * D_MODEL];
__device__ __half g_ff_h[S_PAD * FF_DIM];

__device__ __half g_wqkv_h[NLAYERS * QKV_N * D_MODEL];
__device__ __half g_w1t_h [NLAYERS * FF_DIM * D_MODEL];
__device__ __half g_w2t_h [NLAYERS * D_MODEL * FF_DIM];

// ---------------------------------------------------------------- PTX utils
__device__ __forceinline__ uint32_t smem_u32(const void* p) {
    uint32_t a;
    asm("{ .reg .u64 t; cvta.to.shared.u64 t, %1; cvt.u32.u64 %0, t; }"
        : "=r"(a) : "l"(p));
    return a;
}

#define CP16(s, g) \
    asm volatile("cp.async.cg.shared.global [%0], [%1], 16;" :: "r"(s), "l"(g))
#define CP_COMMIT() asm volatile("cp.async.commit_group;" ::: "memory")
#define CP_WAIT2()  asm volatile("cp.async.wait_group 2;" ::: "memory")

#define LDSM4(r0, r1, r2, r3, a) \
    asm volatile("ldmatrix.sync.aligned.m8n8.x4.shared.b16 {%0,%1,%2,%3}, [%4];" \
                 : "=r"(r0), "=r"(r1), "=r"(r2), "=r"(r3) : "r"(a))

#define MMA16816(c, a, b0, b1)                                                \
    asm volatile("mma.sync.aligned.m16n8k16.row.col.f32.f16.f16.f32 "         \
                 "{%0,%1,%2,%3}, {%4,%5,%6,%7}, {%8,%9}, {%0,%1,%2,%3};"      \
                 : "+f"((c)[0]), "+f"((c)[1]), "+f"((c)[2]), "+f"((c)[3])     \
                 : "r"((a)[0]), "r"((a)[1]), "r"((a)[2]), "r"((a)[3]),        \
                   "r"(b0), "r"(b1))

// ----------------------------------------------------------- block LN reduce
__device__ __forceinline__ float2 block_meanvar(float x0, float x1,
                                                float* shs, float* shss,
                                                float* smu, float* srstd)
{
    __syncthreads();
    int t = threadIdx.x;
    float s  = x0 + x1;
    float ss = x0 * x0 + x1 * x1;
    #pragma unroll
    for (int o = 16; o; o >>= 1) {
        s  += __shfl_xor_sync(0xffffffffu, s, o);
        ss += __shfl_xor_sync(0xffffffffu, ss, o);
    }
    int w = t >> 5, lane = t & 31;
    if (lane == 0) { shs[w] = s; shss[w] = ss; }
    __syncthreads();
    if (t == 0) {
        float a = 0.f, c = 0.f;
        #pragma unroll
        for (int i = 0; i < 8; ++i) { a += shs[i]; c += shss[i]; }
        float mu  = a * (1.0f / D_MODEL);
        float var = c * (1.0f / D_MODEL) - mu * mu;
        *smu = mu;
        *srstd = rsqrtf(var + LN_EPS);
    }
    __syncthreads();
    return make_float2(*smu, *srstd);
}

// ---------------------------------------------------------------- LayerNorm
__global__ void __launch_bounds__(256) ln_kernel(
    const float* __restrict__ in, const float* __restrict__ gamma,
    const float* __restrict__ beta, float* __restrict__ out,
    __half* __restrict__ outH)
{
    __shared__ float shs[8], shss[8], smu, srstd;
    int r = blockIdx.x;
    int t = threadIdx.x;
    const float* row = in + (size_t)r * D_MODEL;
    float x0 = row[t], x1 = row[t + 256];
    float2 mv = block_meanvar(x0, x1, shs, shss, &smu, &srstd);
    float y0 = (x0 - mv.x) * mv.y * gamma[t]       + beta[t];
    float y1 = (x1 - mv.x) * mv.y * gamma[t + 256] + beta[t + 256];
    size_t o0 = (size_t)r * D_MODEL + t;
    if (out) { out[o0] = y0; out[o0 + 256] = y1; }
    outH[o0]       = __float2half_rn(y0);
    outH[o0 + 256] = __float2half_rn(y1);
}

// Fused: t = LN2(inA + inB0 + inB1 + inB2); optional write; hn = LN_in(t).
__global__ void __launch_bounds__(256) ln2_lnin_kernel(
    const float* __restrict__ inA, const float* __restrict__ inB,
    const float* __restrict__ g2, const float* __restrict__ b2,
    float* __restrict__ outT,
    const float* __restrict__ gi, const float* __restrict__ bi,
    float* __restrict__ hn, __half* __restrict__ hnH)
{
    __shared__ float shs[8], shss[8], smu, srstd;
    int r = blockIdx.x;
    int t = threadIdx.x;
    size_t o0 = (size_t)r * D_MODEL + t;
    const size_t PS = (size_t)S_PAD * D_MODEL;
    float x0 = inA[o0]       + inB[o0]       + inB[o0 + PS]       + inB[o0 + 2 * PS];
    float x1 = inA[o0 + 256] + inB[o0 + 256] + inB[o0 + PS + 256] + inB[o0 + 2 * PS + 256];
    float2 mv = block_meanvar(x0, x1, shs, shss, &smu, &srstd);
    float t0 = (x0 - mv.x) * mv.y * g2[t]       + b2[t];
    float t1 = (x1 - mv.x) * mv.y * g2[t + 256] + b2[t + 256];
    if (outT) { outT[o0] = t0; outT[o0 + 256] = t1; }
    if (gi) {
        float2 mv2 = block_meanvar(t0, t1, shs, shss, &smu, &srstd);
        float u0 = (t0 - mv2.x) * mv2.y * gi[t]       + bi[t];
        float u1 = (t1 - mv2.x) * mv2.y * gi[t + 256] + bi[t + 256];
        hn[o0] = u0; hn[o0 + 256] = u1;
        hnH[o0]       = __float2half_rn(u0);
        hnH[o0 + 256] = __float2half_rn(u1);
    }
}

// ------------------------------------- single-launch weight prep (all layers)
// 64(K) x 64(N) tiles; plain fp16 weights (single buffer).
__device__ __forceinline__ void tile64_transpose_h(
    const float* __restrict__ src, __half* __restrict__ dst,
    int K, int N, int n0, int k0, int tid)
{
    __shared__ float t[64][66];
    int tx = tid & 31, ty = tid >> 5;
    #pragma unroll
    for (int kk = ty; kk < 64; kk += 8) {
        float2 v = *reinterpret_cast<const float2*>(
            src + (size_t)(k0 + kk) * N + n0 + 2 * tx);
        t[2 * tx][kk]     = v.x;
        t[2 * tx + 1][kk] = v.y;
    }
    __syncthreads();
    #pragma unroll
    for (int it = 0; it < 8; ++it) {
        int nn = it * 8 + ty;
        float2 v = *reinterpret_cast<const float2*>(&t[nn][2 * tx]);
        __half2 hh;
        hh.x = __float2half_rn(v.x);
        hh.y = __float2half_rn(v.y);
        *reinterpret_cast<__half2*>(
            dst + (size_t)(n0 + nn) * K + k0 + 2 * tx) = hh;
    }
}

#define PREP_PER_LAYER 704
#define PREP_TRANS_BLOCKS (PREP_PER_LAYER * NLAYERS)
#define PREP_BIAS_BLOCKS 48
#define PREP_BLOCKS (PREP_TRANS_BLOCKS + PREP_BIAS_BLOCKS)

__global__ void __launch_bounds__(256) prep_all(
    const float* __restrict__ wq, const float* __restrict__ wk,
    const float* __restrict__ wv, const float* __restrict__ w1,
    const float* __restrict__ w2,
    const float* __restrict__ bq, const float* __restrict__ bk,
    const float* __restrict__ bv,
    __half* __restrict__ wqkv_h, __half* __restrict__ w1t_h,
    __half* __restrict__ w2t_h, float* __restrict__ bqkv)
{
    int id = blockIdx.x;
    int tid = threadIdx.x;
    if (id >= PREP_TRANS_BLOCKS) {
        int i = (id - PREP_TRANS_BLOCKS) * 256 + tid;
        int l = i / QKV_N, c = i % QKV_N;
        float v;
        if (c < 512)       v = bq[l * 512 + c];
        else if (c < 1024) v = bk[l * 512 + c - 512];
        else               v = bv[l * 512 + c - 1024];
        bqkv[i] = v;
        return;
    }
    int l = id / PREP_PER_LAYER;
    int r = id % PREP_PER_LAYER;
    if (r < 192) {
        int which = r >> 6;
        int t = r & 63;
        const float* src = (which == 0) ? wq : (which == 1) ? wk : wv;
        src += (size_t)l * 512 * 512;
        size_t doff = (size_t)l * QKV_N * 512 + (size_t)which * 512 * 512;
        tile64_transpose_h(src, wqkv_h + doff,
                           512, 512, (t & 7) * 64, (t >> 3) * 64, tid);
    } else if (r < 448) {
        int t = r - 192;
        const float* src = w1 + (size_t)l * 512 * 2048;
        size_t doff = (size_t)l * FF_DIM * 512;
        tile64_transpose_h(src, w1t_h + doff,
                           512, 2048, (t & 31) * 64, (t >> 5) * 64, tid);
    } else {
        int t = r - 448;
        const float* src = w2 + (size_t)l * 2048 * 512;
        size_t doff = (size_t)l * D_MODEL * FF_DIM;
        tile64_transpose_h(src, w2t_h + doff,
                           2048, 512, (t & 7) * 64, (t >> 3) * 64, tid);
    }
}

// ------------------------------------------------------------- mma.sync GEMM
// single-pass fp16: C = A*B. BM=128, BN=64, BK=32, 4-stage cp.async,
// 8 warps (4x2). gridDim.z>1 -> split-K (z=0 full epilogue, z>=1 raw
// partials -> outF2 + (z-1)*S_PAD*D_MODEL).
#define A_OFF   0
#define B_OFF   8192
#define STAGE_BYTES 12288
#define GEMM_SMEM (4 * STAGE_BYTES)

__device__ __forceinline__ uint32_t phys(int r, int c) {
    return (uint32_t)(r * 64 + ((c ^ (r & 3)) << 4));
}

__global__ void __launch_bounds__(256, 2) gemm_tc(
    const __half* __restrict__ A, const __half* __restrict__ B,
    const float* __restrict__ bias, const float* __restrict__ res,
    float* __restrict__ outF, float* __restrict__ outF2,
    __half* __restrict__ outH, int Klen, int ldK, int N)
{
    extern __shared__ char smraw[];
    const uint32_t sb = smem_u32(smraw);

    const int tid  = threadIdx.x;
    const int lane = tid & 31;
    const int wid  = tid >> 5;
    const int wm   = wid >> 1;
    const int wn   = wid & 1;
    const int m0   = blockIdx.x * 128;
    const int n0   = blockIdx.y * 64;
    const int kz   = blockIdx.z;
    const int koff = kz * Klen;

    const __half* a0 = A + (size_t)m0 * ldK + koff;
    const __half* b0 = B + (size_t)n0 * ldK + koff;

    const int r0c = tid >> 2, cc = tid & 3;
    const int r1c = r0c + 64;
    const uint32_t s0 = phys(r0c, cc), s1 = phys(r1c, cc);

    float acc[2][4][4];
    #pragma unroll
    for (int i = 0; i < 2; ++i)
        #pragma unroll
        for (int j = 0; j < 4; ++j)
            #pragma unroll
            for (int k = 0; k < 4; ++k) acc[i][j][k] = 0.f;

    const int NC = Klen >> 5;

    auto issue = [&](int c) {
        const uint32_t st = sb + (uint32_t)(c & 3) * STAGE_BYTES;
        const int k0 = c << 5;
        const size_t go0 = (size_t)r0c * ldK + k0 + cc * 8;
        const size_t go1 = (size_t)r1c * ldK + k0 + cc * 8;
        CP16(st + A_OFF + s0, a0 + go0);
        CP16(st + A_OFF + s1, a0 + go1);
        CP16(st + B_OFF + s0, b0 + go0);
    };

    issue(0); CP_COMMIT();
    issue(1); CP_COMMIT();
    issue(2); CP_COMMIT();

    const int lr = lane & 15, lc = lane >> 4;
    const int bg = lane >> 3, bi = lane & 7;
    const int arow0 = wm * 32 + lr;
    const int arow1 = arow0 + 16;
    const int browb = wn * 32 + ((bg >> 1) << 3) + bi;

    for (int c = 0; c < NC; ++c) {
        CP_WAIT2();
        __syncthreads();

        const uint32_t st = sb + (uint32_t)(c & 3) * STAGE_BYTES;
        #pragma unroll
        for (int ks = 0; ks < 2; ++ks) {
            const int ca = ks * 2 + lc;
            const int cb = ks * 2 + (bg & 1);
            uint32_t a0f[4], a1f[4];
            uint32_t bh[4], bh2[4];
            LDSM4(a0f[0], a0f[1], a0f[2], a0f[3], st + A_OFF + phys(arow0, ca));
            LDSM4(a1f[0], a1f[1], a1f[2], a1f[3], st + A_OFF + phys(arow1, ca));
            LDSM4(bh[0], bh[1], bh[2], bh[3],     st + B_OFF + phys(browb, cb));
            LDSM4(bh2[0], bh2[1], bh2[2], bh2[3], st + B_OFF + phys(browb + 16, cb));

            MMA16816(acc[0][0], a0f, bh[0],  bh[1]);
            MMA16816(acc[0][1], a0f, bh[2],  bh[3]);
            MMA16816(acc[0][2], a0f, bh2[0], bh2[1]);
            MMA16816(acc[0][3], a0f, bh2[2], bh2[3]);
            MMA16816(acc[1][0], a1f, bh[0],  bh[1]);
            MMA16816(acc[1][1], a1f, bh[2],  bh[3]);
            MMA16816(acc[1][2], a1f, bh2[0], bh2[1]);
            MMA16816(acc[1][3], a1f, bh2[2], bh2[3]);
        }
        if (c + 3 < NC) issue(c + 3);
        CP_COMMIT();
    }

    // ------------------------------------------------------------- epilogue
    const int erow = (lane >> 2);
    const int ecol = (lane & 3) * 2;
    #pragma unroll
    for (int mt = 0; mt < 2; ++mt) {
        #pragma unroll
        for (int half = 0; half < 2; ++half) {
            const int row = m0 + wm * 32 + mt * 16 + erow + half * 8;
            #pragma unroll
            for (int nt = 0; nt < 4; ++nt) {
                const int col = n0 + wn * 32 + nt * 8 + ecol;
                float v0 = acc[mt][nt][half * 2 + 0];
                float v1 = acc[mt][nt][half * 2 + 1];
                if (kz >= 1) {
                    *reinterpret_cast<float2*>(
                        outF2 + (size_t)(kz - 1) * S_PAD * D_MODEL +
                        (size_t)row * N + col) = make_float2(v0, v1);
                    continue;
                }
                v0 += __ldg(bias + col);
                v1 += __ldg(bias + col + 1);
                if (res) {
                    const float2 r2 = *reinterpret_cast<const float2*>(
                        res + (size_t)row * N + col);
                    v0 += r2.x; v1 += r2.y;
                }
                if (outF)
                    *reinterpret_cast<float2*>(outF + (size_t)row * N + col) =
                        make_float2(v0, v1);
                if (outH) {
                    __half2 hh;
                    hh.x = __float2half_rn(v0);
                    hh.y = __float2half_rn(v1);
                    *reinterpret_cast<__half2*>(outH + (size_t)row * N + col) = hh;
                }
            }
        }
    }
}

// ---------------------------------------------- chunked sparse attention v6
#define ATTN_THREADS 512

__global__ void __launch_bounds__(ATTN_THREADS) attn_chunk_kernel(
    const float* __restrict__ QKV,
    const float* __restrict__ hn, float* __restrict__ attnOut)
{
    __shared__ float Ks[64][68];
    __shared__ float Vs[60][68];
    __shared__ float Qs[40][68];

    const int i    = blockIdx.x;
    const int h    = blockIdx.y;
    const int tid  = threadIdx.x;
    const int w    = tid >> 5;
    const int lane = tid & 31;
    const int hoff = h * 64;

    const int bodyLo = max(0, 32 * i - 20);
    const int nb     = 32 * (i + 1) - bodyLo;
    const int nrc    = (i < 31) ? 8 : 0;
    const int nk     = nrc + nb;
    const int nq     = 32 + nrc;

    for (int e = tid; e < nk * 16; e += ATTN_THREADS) {
        int j = e >> 4, d = (e & 15) << 2;
        int kg = (j < nrc) ? (8 * i + j) : (UB + bodyLo + (j - nrc));
        size_t base = (size_t)kg * QKV_N + hoff + d;
        *reinterpret_cast<float4*>(&Ks[j][d]) =
            *reinterpret_cast<const float4*>(QKV + base + 512);
        *reinterpret_cast<float4*>(&Vs[j][d]) =
            *reinterpret_cast<const float4*>(QKV + base + 1024);
    }
    for (int e = tid + nk * 16; e < 64 * 16; e += ATTN_THREADS) {
        int j = e >> 4, d = (e & 15) << 2;
        *reinterpret_cast<float4*>(&Ks[j][d]) = make_float4(0.f, 0.f, 0.f, 0.f);
    }
    for (int e = tid; e < nq * 16; e += ATTN_THREADS) {
        int qq = e >> 4, d = (e & 15) << 2;
        int row = (qq < nrc) ? (8 * i + qq) : (UB + 32 * i + (qq - nrc));
        float4 q = *reinterpret_cast<const float4*>(
            QKV + (size_t)row * QKV_N + hoff + d);
        *reinterpret_cast<float4*>(&Qs[qq][d]) =
            make_float4(q.x * 0.125f, q.y * 0.125f, q.z * 0.125f, q.w * 0.125f);
    }
    __syncthreads();

    const int lim1 = nk - 32;
    const int nqw = (nq - w + 15) >> 4;

    float s0[3] = {0.f, 0.f, 0.f}, s1[3] = {0.f, 0.f, 0.f};
    #pragma unroll 4
    for (int d = 0; d < 64; d += 4) {
        float4 k0 = *reinterpret_cast<const float4*>(&Ks[lane][d]);
        float4 k1 = *reinterpret_cast<const float4*>(&Ks[lane + 32][d]);
        #pragma unroll
        for (int t = 0; t < 3; ++t) {
            if (t < nqw) {
                float4 q = *reinterpret_cast<const float4*>(&Qs[w + 16 * t][d]);
                s0[t] = fmaf(q.x, k0.x, s0[t]);
                s0[t] = fmaf(q.y, k0.y, s0[t]);
                s0[t] = fmaf(q.z, k0.z, s0[t]);
                s0[t] = fmaf(q.w, k0.w, s0[t]);
                s1[t] = fmaf(q.x, k1.x, s1[t]);
                s1[t] = fmaf(q.y, k1.y, s1[t]);
                s1[t] = fmaf(q.z, k1.z, s1[t]);
                s1[t] = fmaf(q.w, k1.w, s1[t]);
            }
        }
    }

    float e0[3], e1[3], inv[3];
    #pragma unroll
    for (int t = 0; t < 3; ++t) {
        if (t >= nqw) { e0[t] = 0.f; e1[t] = 0.f; inv[t] = 0.f; continue; }
        float a0 = s0[t];
        float a1 = (lane < lim1) ? s1[t] : -1e30f;
        float m = fmaxf(a0, a1);
        #pragma unroll
        for (int o = 16; o; o >>= 1) m = fmaxf(m, __shfl_xor_sync(0xffffffffu, m, o));
        e0[t] = __expf(a0 - m);
        e1[t] = (lane < lim1) ? __expf(a1 - m) : 0.f;
        float ssum = e0[t] + e1[t];
        #pragma unroll
        for (int o = 16; o; o >>= 1) ssum += __shfl_xor_sync(0xffffffffu, ssum, o);
        inv[t] = 1.0f / ssum;
    }

    float o0[3] = {0.f, 0.f, 0.f}, o1[3] = {0.f, 0.f, 0.f};
    #pragma unroll 4
    for (int jj = 0; jj < 32; ++jj) {
        float2 v = *reinterpret_cast<const float2*>(&Vs[jj][2 * lane]);
        #pragma unroll
        for (int t = 0; t < 3; ++t) {
            float p = __shfl_sync(0xffffffffu, e0[t], jj);
            o0[t] = fmaf(p, v.x, o0[t]);
            o1[t] = fmaf(p, v.y, o1[t]);
        }
    }
    for (int jj = 0; jj < lim1; ++jj) {
        float2 v = *reinterpret_cast<const float2*>(&Vs[jj + 32][2 * lane]);
        #pragma unroll
        for (int t = 0; t < 3; ++t) {
            float p = __shfl_sync(0xffffffffu, e1[t], jj);
            o0[t] = fmaf(p, v.x, o0[t]);
            o1[t] = fmaf(p, v.y, o1[t]);
        }
    }

    #pragma unroll
    for (int t = 0; t < 3; ++t) {
        if (t >= nqw) continue;
        const int qq = w + 16 * t;
        const int row = (qq < nrc) ? (8 * i + qq) : (UB + 32 * i + (qq - nrc));
        const size_t off = (size_t)row * D_MODEL + hoff + 2 * lane;
        const float2 hv = *reinterpret_cast<const float2*>(hn + off);
        *reinterpret_cast<float2*>(attnOut + off) =
            make_float2(o0[t] * inv[t] + hv.x, o1[t] * inv[t] + hv.y);
    }
}

// ------------------------------------------------------------------- driver
extern "C" void kernel_launch(void* const* d_in, const int* in_sizes, int n_in,
                              void* d_out, int out_size)
{
    (void)in_sizes; (void)n_in; (void)out_size;

    const float* x      = (const float*)d_in[0];
    const float* lnin_s = (const float*)d_in[2];
    const float* lnin_b = (const float*)d_in[3];
    const float* wq     = (const float*)d_in[4];
    const float* bq     = (const float*)d_in[5];
    const float* wk     = (const float*)d_in[6];
    const float* bk     = (const float*)d_in[7];
    const float* wv     = (const float*)d_in[8];
    const float* bv     = (const float*)d_in[9];
    const float* ln1_s  = (const float*)d_in[10];
    const float* ln1_b  = (const float*)d_in[11];
    const float* w1     = (const float*)d_in[12];
    const float* b1     = (const float*)d_in[13];
    const float* w2     = (const float*)d_in[14];
    const float* b2     = (const float*)d_in[15];
    const float* ln2_s  = (const float*)d_in[16];
    const float* ln2_b  = (const float*)d_in[17];
    float* out = (float*)d_out;

    float *p_hn, *p_attn, *p_ff2a, *p_ff2b, *p_qkv, *p_bqkv;
    __half *p_hn_h, *p_y_h, *p_ff_h;
    __half *p_wqkv_h, *p_w1t_h, *p_w2t_h;
    cudaGetSymbolAddress((void**)&p_hn,    g_hn);
    cudaGetSymbolAddress((void**)&p_attn,  g_attn);
    cudaGetSymbolAddress((void**)&p_ff2a,  g_ff2a);
    cudaGetSymbolAddress((void**)&p_ff2b,  g_ff2b);
    cudaGetSymbolAddress((void**)&p_qkv,   g_qkv);
    cudaGetSymbolAddress((void**)&p_bqkv,  g_bqkv);
    cudaGetSymbolAddress((void**)&p_hn_h,  g_hn_h);
    cudaGetSymbolAddress((void**)&p_y_h,   g_y_h);
    cudaGetSymbolAddress((void**)&p_ff_h,  g_ff_h);
    cudaGetSymbolAddress((void**)&p_wqkv_h, g_wqkv_h);
    cudaGetSymbolAddress((void**)&p_w1t_h,  g_w1t_h);
    cudaGetSymbolAddress((void**)&p_w2t_h,  g_w2t_h);

    cudaFuncSetAttribute(gemm_tc, cudaFuncAttributeMaxDynamicSharedMemorySize,
                         GEMM_SMEM);

    dim3 blk(256);
    prep_all<<<PREP_BLOCKS, blk>>>(wq, wk, wv, w1, w2, bq, bk, bv,
                                   p_wqkv_h, p_w1t_h, p_w2t_h, p_bqkv);

    const int MT = S_PAD / 128;   // 10
    for (int l = 0; l < NLAYERS; ++l) {
        size_t oD = (size_t)l * D_MODEL;
        size_t oF = (size_t)l * FF_DIM;

        if (l == 0)
            ln_kernel<<<S_LEN, blk>>>(x, lnin_s, lnin_b, p_hn, p_hn_h);

        // fused QKV, full K: BN=64, grid 10x24 = 240
        gemm_tc<<<dim3(MT, QKV_N / 64), blk, GEMM_SMEM>>>(
            p_hn_h, p_wqkv_h + (size_t)l * QKV_N * 512,
            p_bqkv + (size_t)l * QKV_N, nullptr,
            p_qkv, nullptr, nullptr, 512, 512, QKV_N);
        // chunked sparse attention v6 (+ residual onto hn)
        attn_chunk_kernel<<<dim3(32, 8), ATTN_THREADS>>>(p_qkv, p_hn, p_attn);
        // ln1 -> y fp16
        ln_kernel<<<S_LEN, blk>>>(p_attn, ln1_s + oD, ln1_b + oD,
                                  nullptr, p_y_h);
        // FFN1: BN=64, full K, grid 10x32 = 320
        gemm_tc<<<dim3(MT, FF_DIM / 64), blk, GEMM_SMEM>>>(
            p_y_h, p_w1t_h + (size_t)l * FF_DIM * 512,
            b1 + oF, nullptr,
            nullptr, nullptr, p_ff_h, 512, 512, FF_DIM);
        // FFN2: BN=64, split-K=4, grid 10x8x4 = 320
        gemm_tc<<<dim3(MT, D_MODEL / 64, 4), blk, GEMM_SMEM>>>(
            p_ff_h, p_w2t_h + (size_t)l * D_MODEL * FF_DIM,
            b2 + oD, p_attn,
            p_ff2a, p_ff2b, nullptr, 512, FF_DIM, D_MODEL);
        if (l < NLAYERS - 1) {
            ln2_lnin_kernel<<<S_LEN, blk>>>(
                p_ff2a, p_ff2b, ln2_s + oD, ln2_b + oD, nullptr,
                lnin_s + oD + D_MODEL, lnin_b + oD + D_MODEL,
                p_hn, p_hn_h);
        } else {
            ln2_lnin_kernel<<<S_LEN, blk>>>(
                p_ff2a, p_ff2b, ln2_s + oD, ln2_b + oD, out,
                nullptr, nullptr, nullptr, nullptr);
        }
    }
}

// round 17
// speedup vs baseline: 1.3941x; 1.0042x over previous
#include <cuda_runtime.h>
#include <cuda_fp16.h>
#include <stdint.h>
#include <math.h>

// ---------------------------------------------------------------- constants
#define S_LEN   1272
#define S_PAD   1280
#define D_MODEL 512
#define QKV_N   1536
#define FF_DIM  2048
#define NLAYERS 8
#define UB      248
#define LN_EPS  1e-3f

// ---------------------------------------------------------------- scratch
__device__ float g_hn  [S_PAD * D_MODEL];
__device__ float g_attn[S_PAD * D_MODEL];
__device__ float g_ff2a[S_PAD * D_MODEL];
__device__ float g_ff2b[3 * S_PAD * D_MODEL];   // FFN2 split-K partials
__device__ float g_bqkv[NLAYERS * QKV_N];

__device__ __half g_qkv_h[S_PAD * QKV_N];
__device__ __half g_hn_h[S_PAD * D_MODEL];
__device__ __half g_y_h [S_PAD * D_MODEL];
__device__ __half g_ff_h[S_PAD * FF_DIM];

__device__ __half g_wqkv_h[NLAYERS * QKV_N * D_MODEL];
__device__ __half g_w1t_h [NLAYERS * FF_DIM * D_MODEL];
__device__ __half g_w2t_h [NLAYERS * D_MODEL * FF_DIM];

// ---------------------------------------------------------------- PTX utils
__device__ __forceinline__ uint32_t smem_u32(const void* p) {
    uint32_t a;
    asm("{ .reg .u64 t; cvta.to.shared.u64 t, %1; cvt.u32.u64 %0, t; }"
        : "=r"(a) : "l"(p));
    return a;
}

#define CP16(s, g) \
    asm volatile("cp.async.cg.shared.global [%0], [%1], 16;" :: "r"(s), "l"(g))
#define CP_COMMIT() asm volatile("cp.async.commit_group;" ::: "memory")
#define CP_WAIT1()  asm volatile("cp.async.wait_group 1;" ::: "memory")

#define LDSM4(r0, r1, r2, r3, a) \
    asm volatile("ldmatrix.sync.aligned.m8n8.x4.shared.b16 {%0,%1,%2,%3}, [%4];" \
                 : "=r"(r0), "=r"(r1), "=r"(r2), "=r"(r3) : "r"(a))

#define MMA16816(c, a, b0, b1)                                                \
    asm volatile("mma.sync.aligned.m16n8k16.row.col.f32.f16.f16.f32 "         \
                 "{%0,%1,%2,%3}, {%4,%5,%6,%7}, {%8,%9}, {%0,%1,%2,%3};"      \
                 : "+f"((c)[0]), "+f"((c)[1]), "+f"((c)[2]), "+f"((c)[3])     \
                 : "r"((a)[0]), "r"((a)[1]), "r"((a)[2]), "r"((a)[3]),        \
                   "r"(b0), "r"(b1))

// ----------------------------------------------------------- block LN reduce
__device__ __forceinline__ float2 block_meanvar(float x0, float x1,
                                                float* shs, float* shss,
                                                float* smu, float* srstd)
{
    __syncthreads();
    int t = threadIdx.x;
    float s  = x0 + x1;
    float ss = x0 * x0 + x1 * x1;
    #pragma unroll
    for (int o = 16; o; o >>= 1) {
        s  += __shfl_xor_sync(0xffffffffu, s, o);
        ss += __shfl_xor_sync(0xffffffffu, ss, o);
    }
    int w = t >> 5, lane = t & 31;
    if (lane == 0) { shs[w] = s; shss[w] = ss; }
    __syncthreads();
    if (t == 0) {
        float a = 0.f, c = 0.f;
        #pragma unroll
        for (int i = 0; i < 8; ++i) { a += shs[i]; c += shss[i]; }
        float mu  = a * (1.0f / D_MODEL);
        float var = c * (1.0f / D_MODEL) - mu * mu;
        *smu = mu;
        *srstd = rsqrtf(var + LN_EPS);
    }
    __syncthreads();
    return make_float2(*smu, *srstd);
}

// ---------------------------------------------------------------- LayerNorm
__global__ void __launch_bounds__(256) ln_kernel(
    const float* __restrict__ in, const float* __restrict__ gamma,
    const float* __restrict__ beta, float* __restrict__ out,
    __half* __restrict__ outH)
{
    __shared__ float shs[8], shss[8], smu, srstd;
    int r = blockIdx.x;
    int t = threadIdx.x;
    const float* row = in + (size_t)r * D_MODEL;
    float x0 = row[t], x1 = row[t + 256];
    float2 mv = block_meanvar(x0, x1, shs, shss, &smu, &srstd);
    float y0 = (x0 - mv.x) * mv.y * gamma[t]       + beta[t];
    float y1 = (x1 - mv.x) * mv.y * gamma[t + 256] + beta[t + 256];
    size_t o0 = (size_t)r * D_MODEL + t;
    if (out) { out[o0] = y0; out[o0 + 256] = y1; }
    outH[o0]       = __float2half_rn(y0);
    outH[o0 + 256] = __float2half_rn(y1);
}

// Fused: t = LN2(inA + inB0 + inB1 + inB2); optional write; hn = LN_in(t).
__global__ void __launch_bounds__(256) ln2_lnin_kernel(
    const float* __restrict__ inA, const float* __restrict__ inB,
    const float* __restrict__ g2, const float* __restrict__ b2,
    float* __restrict__ outT,
    const float* __restrict__ gi, const float* __restrict__ bi,
    float* __restrict__ hn, __half* __restrict__ hnH)
{
    __shared__ float shs[8], shss[8], smu, srstd;
    int r = blockIdx.x;
    int t = threadIdx.x;
    size_t o0 = (size_t)r * D_MODEL + t;
    const size_t PS = (size_t)S_PAD * D_MODEL;
    float x0 = inA[o0]       + inB[o0]       + inB[o0 + PS]       + inB[o0 + 2 * PS];
    float x1 = inA[o0 + 256] + inB[o0 + 256] + inB[o0 + PS + 256] + inB[o0 + 2 * PS + 256];
    float2 mv = block_meanvar(x0, x1, shs, shss, &smu, &srstd);
    float t0 = (x0 - mv.x) * mv.y * g2[t]       + b2[t];
    float t1 = (x1 - mv.x) * mv.y * g2[t + 256] + b2[t + 256];
    if (outT) { outT[o0] = t0; outT[o0 + 256] = t1; }
    if (gi) {
        float2 mv2 = block_meanvar(t0, t1, shs, shss, &smu, &srstd);
        float u0 = (t0 - mv2.x) * mv2.y * gi[t]       + bi[t];
        float u1 = (t1 - mv2.x) * mv2.y * gi[t + 256] + bi[t + 256];
        hn[o0] = u0; hn[o0 + 256] = u1;
        hnH[o0]       = __float2half_rn(u0);
        hnH[o0 + 256] = __float2half_rn(u1);
    }
}

// ------------------------------------- single-launch weight prep (all layers)
__device__ __forceinline__ void tile64_transpose_h(
    const float* __restrict__ src, __half* __restrict__ dst,
    int K, int N, int n0, int k0, int tid)
{
    __shared__ float t[64][66];
    int tx = tid & 31, ty = tid >> 5;
    #pragma unroll
    for (int kk = ty; kk < 64; kk += 8) {
        float2 v = *reinterpret_cast<const float2*>(
            src + (size_t)(k0 + kk) * N + n0 + 2 * tx);
        t[2 * tx][kk]     = v.x;
        t[2 * tx + 1][kk] = v.y;
    }
    __syncthreads();
    #pragma unroll
    for (int it = 0; it < 8; ++it) {
        int nn = it * 8 + ty;
        float2 v = *reinterpret_cast<const float2*>(&t[nn][2 * tx]);
        __half2 hh;
        hh.x = __float2half_rn(v.x);
        hh.y = __float2half_rn(v.y);
        *reinterpret_cast<__half2*>(
            dst + (size_t)(n0 + nn) * K + k0 + 2 * tx) = hh;
    }
}

#define PREP_PER_LAYER 704
#define PREP_TRANS_BLOCKS (PREP_PER_LAYER * NLAYERS)
#define PREP_BIAS_BLOCKS 48
#define PREP_BLOCKS (PREP_TRANS_BLOCKS + PREP_BIAS_BLOCKS)

__global__ void __launch_bounds__(256) prep_all(
    const float* __restrict__ wq, const float* __restrict__ wk,
    const float* __restrict__ wv, const float* __restrict__ w1,
    const float* __restrict__ w2,
    const float* __restrict__ bq, const float* __restrict__ bk,
    const float* __restrict__ bv,
    __half* __restrict__ wqkv_h, __half* __restrict__ w1t_h,
    __half* __restrict__ w2t_h, float* __restrict__ bqkv)
{
    int id = blockIdx.x;
    int tid = threadIdx.x;
    if (id >= PREP_TRANS_BLOCKS) {
        int i = (id - PREP_TRANS_BLOCKS) * 256 + tid;
        int l = i / QKV_N, c = i % QKV_N;
        float v;
        if (c < 512)       v = bq[l * 512 + c];
        else if (c < 1024) v = bk[l * 512 + c - 512];
        else               v = bv[l * 512 + c - 1024];
        bqkv[i] = v;
        return;
    }
    int l = id / PREP_PER_LAYER;
    int r = id % PREP_PER_LAYER;
    if (r < 192) {
        int which = r >> 6;
        int t = r & 63;
        const float* src = (which == 0) ? wq : (which == 1) ? wk : wv;
        src += (size_t)l * 512 * 512;
        size_t doff = (size_t)l * QKV_N * 512 + (size_t)which * 512 * 512;
        tile64_transpose_h(src, wqkv_h + doff,
                           512, 512, (t & 7) * 64, (t >> 3) * 64, tid);
    } else if (r < 448) {
        int t = r - 192;
        const float* src = w1 + (size_t)l * 512 * 2048;
        size_t doff = (size_t)l * FF_DIM * 512;
        tile64_transpose_h(src, w1t_h + doff,
                           512, 2048, (t & 31) * 64, (t >> 5) * 64, tid);
    } else {
        int t = r - 448;
        const float* src = w2 + (size_t)l * 2048 * 512;
        size_t doff = (size_t)l * D_MODEL * FF_DIM;
        tile64_transpose_h(src, w2t_h + doff,
                           2048, 512, (t & 7) * 64, (t >> 3) * 64, tid);
    }
}

// ------------------------------------------------------------- mma.sync GEMM
// single-pass fp16, BK=64 (two 32-wide k-halves per stage -> half the
// barriers). BM=128, BN=64, 3-stage cp.async, 8 warps (4x2).
// gridDim.z>1 -> split-K (z=0 full epilogue, z>=1 raw partials).
#define A0_OFF  0
#define A1_OFF  8192
#define B0_OFF  16384
#define B1_OFF  20480
#define STAGE_BYTES 24576
#define GEMM_SMEM (3 * STAGE_BYTES)

__device__ __forceinline__ uint32_t phys(int r, int c) {
    return (uint32_t)(r * 64 + ((c ^ (r & 3)) << 4));
}

__global__ void __launch_bounds__(256, 2) gemm_tc(
    const __half* __restrict__ A, const __half* __restrict__ B,
    const float* __restrict__ bias, const float* __restrict__ res,
    float* __restrict__ outF, float* __restrict__ outF2,
    __half* __restrict__ outH, int Klen, int ldK, int N)
{
    extern __shared__ char smraw[];
    const uint32_t sb = smem_u32(smraw);

    const int tid  = threadIdx.x;
    const int lane = tid & 31;
    const int wid  = tid >> 5;
    const int wm   = wid >> 1;
    const int wn   = wid & 1;
    const int m0   = blockIdx.x * 128;
    const int n0   = blockIdx.y * 64;
    const int kz   = blockIdx.z;
    const int koff = kz * Klen;

    const __half* a0 = A + (size_t)m0 * ldK + koff;
    const __half* b0 = B + (size_t)n0 * ldK + koff;

    const int r0c = tid >> 2, cc = tid & 3;
    const int r1c = r0c + 64;
    const uint32_t s0 = phys(r0c, cc), s1 = phys(r1c, cc);

    float acc[2][4][4];
    #pragma unroll
    for (int i = 0; i < 2; ++i)
        #pragma unroll
        for (int j = 0; j < 4; ++j)
            #pragma unroll
            for (int k = 0; k < 4; ++k) acc[i][j][k] = 0.f;

    const int NC = Klen >> 6;   // BK=64 chunks

    auto issue = [&](int c) {
        const uint32_t st = sb + (uint32_t)(c % 3) * STAGE_BYTES;
        const int k0 = c << 6;
        const size_t go0 = (size_t)r0c * ldK + k0 + cc * 8;
        const size_t go1 = (size_t)r1c * ldK + k0 + cc * 8;
        CP16(st + A0_OFF + s0, a0 + go0);
        CP16(st + A0_OFF + s1, a0 + go1);
        CP16(st + A1_OFF + s0, a0 + go0 + 32);
        CP16(st + A1_OFF + s1, a0 + go1 + 32);
        CP16(st + B0_OFF + s0, b0 + go0);
        CP16(st + B1_OFF + s0, b0 + go0 + 32);
    };

    issue(0); CP_COMMIT();
    issue(1); CP_COMMIT();

    const int lr = lane & 15, lc = lane >> 4;
    const int bg = lane >> 3, bi = lane & 7;
    const int arow0 = wm * 32 + lr;
    const int arow1 = arow0 + 16;
    const int browb = wn * 32 + ((bg >> 1) << 3) + bi;

    for (int c = 0; c < NC; ++c) {
        CP_WAIT1();
        __syncthreads();

        const uint32_t st = sb + (uint32_t)(c % 3) * STAGE_BYTES;
        #pragma unroll
        for (int ks = 0; ks < 4; ++ks) {
            const uint32_t aoff = (ks >> 1) ? A1_OFF : A0_OFF;
            const uint32_t boff = (ks >> 1) ? B1_OFF : B0_OFF;
            const int ca = (ks & 1) * 2 + lc;
            const int cb = (ks & 1) * 2 + (bg & 1);
            uint32_t a0f[4], a1f[4];
            uint32_t bh[4], bh2[4];
            LDSM4(a0f[0], a0f[1], a0f[2], a0f[3], st + aoff + phys(arow0, ca));
            LDSM4(a1f[0], a1f[1], a1f[2], a1f[3], st + aoff + phys(arow1, ca));
            LDSM4(bh[0], bh[1], bh[2], bh[3],     st + boff + phys(browb, cb));
            LDSM4(bh2[0], bh2[1], bh2[2], bh2[3], st + boff + phys(browb + 16, cb));

            MMA16816(acc[0][0], a0f, bh[0],  bh[1]);
            MMA16816(acc[0][1], a0f, bh[2],  bh[3]);
            MMA16816(acc[0][2], a0f, bh2[0], bh2[1]);
            MMA16816(acc[0][3], a0f, bh2[2], bh2[3]);
            MMA16816(acc[1][0], a1f, bh[0],  bh[1]);
            MMA16816(acc[1][1], a1f, bh[2],  bh[3]);
            MMA16816(acc[1][2], a1f, bh2[0], bh2[1]);
            MMA16816(acc[1][3], a1f, bh2[2], bh2[3]);
        }
        if (c + 2 < NC) issue(c + 2);
        CP_COMMIT();
    }

    // ------------------------------------------------------------- epilogue
    const int erow = (lane >> 2);
    const int ecol = (lane & 3) * 2;
    #pragma unroll
    for (int mt = 0; mt < 2; ++mt) {
        #pragma unroll
        for (int half = 0; half < 2; ++half) {
            const int row = m0 + wm * 32 + mt * 16 + erow + half * 8;
            #pragma unroll
            for (int nt = 0; nt < 4; ++nt) {
                const int col = n0 + wn * 32 + nt * 8 + ecol;
                float v0 = acc[mt][nt][half * 2 + 0];
                float v1 = acc[mt][nt][half * 2 + 1];
                if (kz >= 1) {
                    *reinterpret_cast<float2*>(
                        outF2 + (size_t)(kz - 1) * S_PAD * D_MODEL +
                        (size_t)row * N + col) = make_float2(v0, v1);
                    continue;
                }
                v0 += __ldg(bias + col);
                v1 += __ldg(bias + col + 1);
                if (res) {
                    const float2 r2 = *reinterpret_cast<const float2*>(
                        res + (size_t)row * N + col);
                    v0 += r2.x; v1 += r2.y;
                }
                if (outF)
                    *reinterpret_cast<float2*>(outF + (size_t)row * N + col) =
                        make_float2(v0, v1);
                if (outH) {
                    __half2 hh;
                    hh.x = __float2half_rn(v0);
                    hh.y = __float2half_rn(v1);
                    *reinterpret_cast<__half2*>(outH + (size_t)row * N + col) = hh;
                }
            }
        }
    }
}

// ---------------------------------------------- chunked sparse attention v7
// grid (32, 8), 512 threads. fp16 QKV buffer (half the staging bytes),
// converted to fp32 smem tiles. Key-major float4 score loop (v6 structure).
#define ATTN_THREADS 512

__global__ void __launch_bounds__(ATTN_THREADS) attn_chunk_kernel(
    const __half* __restrict__ QKV,
    const float* __restrict__ hn, float* __restrict__ attnOut)
{
    __shared__ float Ks[64][68];
    __shared__ float Vs[60][68];
    __shared__ float Qs[40][68];

    const int i    = blockIdx.x;
    const int h    = blockIdx.y;
    const int tid  = threadIdx.x;
    const int w    = tid >> 5;
    const int lane = tid & 31;
    const int hoff = h * 64;

    const int bodyLo = max(0, 32 * i - 20);
    const int nb     = 32 * (i + 1) - bodyLo;
    const int nrc    = (i < 31) ? 8 : 0;
    const int nk     = nrc + nb;
    const int nq     = 32 + nrc;

    // stage K and V: one uint4 (8 halves) per iteration, convert to fp32
    for (int e = tid; e < nk * 8; e += ATTN_THREADS) {
        int j = e >> 3, d = (e & 7) << 3;
        int kg = (j < nrc) ? (8 * i + j) : (UB + bodyLo + (j - nrc));
        size_t base = (size_t)kg * QKV_N + hoff + d;
        uint4 kraw = *reinterpret_cast<const uint4*>(QKV + base + 512);
        uint4 vraw = *reinterpret_cast<const uint4*>(QKV + base + 1024);
        const __half2* kh = reinterpret_cast<const __half2*>(&kraw);
        const __half2* vh = reinterpret_cast<const __half2*>(&vraw);
        #pragma unroll
        for (int p = 0; p < 4; ++p) {
            float2 kf = __half22float2(kh[p]);
            float2 vf = __half22float2(vh[p]);
            Ks[j][d + 2 * p]     = kf.x;
            Ks[j][d + 2 * p + 1] = kf.y;
            Vs[j][d + 2 * p]     = vf.x;
            Vs[j][d + 2 * p + 1] = vf.y;
        }
    }
    // zero-fill K rows [nk, 64)
    for (int e = tid + nk * 8; e < 64 * 8; e += ATTN_THREADS) {
        int j = e >> 3, d = (e & 7) << 3;
        #pragma unroll
        for (int p = 0; p < 8; ++p) Ks[j][d + p] = 0.f;
    }
    // stage Q (scale folded)
    for (int e = tid; e < nq * 8; e += ATTN_THREADS) {
        int qq = e >> 3, d = (e & 7) << 3;
        int row = (qq < nrc) ? (8 * i + qq) : (UB + 32 * i + (qq - nrc));
        uint4 qraw = *reinterpret_cast<const uint4*>(
            QKV + (size_t)row * QKV_N + hoff + d);
        const __half2* qh = reinterpret_cast<const __half2*>(&qraw);
        #pragma unroll
        for (int p = 0; p < 4; ++p) {
            float2 qf = __half22float2(qh[p]);
            Qs[qq][d + 2 * p]     = qf.x * 0.125f;
            Qs[qq][d + 2 * p + 1] = qf.y * 0.125f;
        }
    }
    __syncthreads();

    const int lim1 = nk - 32;
    const int nqw = (nq - w + 15) >> 4;

    float s0[3] = {0.f, 0.f, 0.f}, s1[3] = {0.f, 0.f, 0.f};
    #pragma unroll 4
    for (int d = 0; d < 64; d += 4) {
        float4 k0 = *reinterpret_cast<const float4*>(&Ks[lane][d]);
        float4 k1 = *reinterpret_cast<const float4*>(&Ks[lane + 32][d]);
        #pragma unroll
        for (int t = 0; t < 3; ++t) {
            if (t < nqw) {
                float4 q = *reinterpret_cast<const float4*>(&Qs[w + 16 * t][d]);
                s0[t] = fmaf(q.x, k0.x, s0[t]);
                s0[t] = fmaf(q.y, k0.y, s0[t]);
                s0[t] = fmaf(q.z, k0.z, s0[t]);
                s0[t] = fmaf(q.w, k0.w, s0[t]);
                s1[t] = fmaf(q.x, k1.x, s1[t]);
                s1[t] = fmaf(q.y, k1.y, s1[t]);
                s1[t] = fmaf(q.z, k1.z, s1[t]);
                s1[t] = fmaf(q.w, k1.w, s1[t]);
            }
        }
    }

    float e0[3], e1[3], inv[3];
    #pragma unroll
    for (int t = 0; t < 3; ++t) {
        if (t >= nqw) { e0[t] = 0.f; e1[t] = 0.f; inv[t] = 0.f; continue; }
        float a0 = s0[t];
        float a1 = (lane < lim1) ? s1[t] : -1e30f;
        float m = fmaxf(a0, a1);
        #pragma unroll
        for (int o = 16; o; o >>= 1) m = fmaxf(m, __shfl_xor_sync(0xffffffffu, m, o));
        e0[t] = __expf(a0 - m);
        e1[t] = (lane < lim1) ? __expf(a1 - m) : 0.f;
        float ssum = e0[t] + e1[t];
        #pragma unroll
        for (int o = 16; o; o >>= 1) ssum += __shfl_xor_sync(0xffffffffu, ssum, o);
        inv[t] = 1.0f / ssum;
    }

    float o0[3] = {0.f, 0.f, 0.f}, o1[3] = {0.f, 0.f, 0.f};
    #pragma unroll 4
    for (int jj = 0; jj < 32; ++jj) {
        float2 v = *reinterpret_cast<const float2*>(&Vs[jj][2 * lane]);
        #pragma unroll
        for (int t = 0; t < 3; ++t) {
            float p = __shfl_sync(0xffffffffu, e0[t], jj);
            o0[t] = fmaf(p, v.x, o0[t]);
            o1[t] = fmaf(p, v.y, o1[t]);
        }
    }
    for (int jj = 0; jj < lim1; ++jj) {
        float2 v = *reinterpret_cast<const float2*>(&Vs[jj + 32][2 * lane]);
        #pragma unroll
        for (int t = 0; t < 3; ++t) {
            float p = __shfl_sync(0xffffffffu, e1[t], jj);
            o0[t] = fmaf(p, v.x, o0[t]);
            o1[t] = fmaf(p, v.y, o1[t]);
        }
    }

    #pragma unroll
    for (int t = 0; t < 3; ++t) {
        if (t >= nqw) continue;
        const int qq = w + 16 * t;
        const int row = (qq < nrc) ? (8 * i + qq) : (UB + 32 * i + (qq - nrc));
        const size_t off = (size_t)row * D_MODEL + hoff + 2 * lane;
        const float2 hv = *reinterpret_cast<const float2*>(hn + off);
        *reinterpret_cast<float2*>(attnOut + off) =
            make_float2(o0[t] * inv[t] + hv.x, o1[t] * inv[t] + hv.y);
    }
}

// ------------------------------------------------------------------- driver
extern "C" void kernel_launch(void* const* d_in, const int* in_sizes, int n_in,
                              void* d_out, int out_size)
{
    (void)in_sizes; (void)n_in; (void)out_size;

    const float* x      = (const float*)d_in[0];
    const float* lnin_s = (const float*)d_in[2];
    const float* lnin_b = (const float*)d_in[3];
    const float* wq     = (const float*)d_in[4];
    const float* bq     = (const float*)d_in[5];
    const float* wk     = (const float*)d_in[6];
    const float* bk     = (const float*)d_in[7];
    const float* wv     = (const float*)d_in[8];
    const float* bv     = (const float*)d_in[9];
    const float* ln1_s  = (const float*)d_in[10];
    const float* ln1_b  = (const float*)d_in[11];
    const float* w1     = (const float*)d_in[12];
    const float* b1     = (const float*)d_in[13];
    const float* w2     = (const float*)d_in[14];
    const float* b2     = (const float*)d_in[15];
    const float* ln2_s  = (const float*)d_in[16];
    const float* ln2_b  = (const float*)d_in[17];
    float* out = (float*)d_out;

    float *p_hn, *p_attn, *p_ff2a, *p_ff2b, *p_bqkv;
    __half *p_qkv_h, *p_hn_h, *p_y_h, *p_ff_h;
    __half *p_wqkv_h, *p_w1t_h, *p_w2t_h;
    cudaGetSymbolAddress((void**)&p_hn,    g_hn);
    cudaGetSymbolAddress((void**)&p_attn,  g_attn);
    cudaGetSymbolAddress((void**)&p_ff2a,  g_ff2a);
    cudaGetSymbolAddress((void**)&p_ff2b,  g_ff2b);
    cudaGetSymbolAddress((void**)&p_bqkv,  g_bqkv);
    cudaGetSymbolAddress((void**)&p_qkv_h, g_qkv_h);
    cudaGetSymbolAddress((void**)&p_hn_h,  g_hn_h);
    cudaGetSymbolAddress((void**)&p_y_h,   g_y_h);
    cudaGetSymbolAddress((void**)&p_ff_h,  g_ff_h);
    cudaGetSymbolAddress((void**)&p_wqkv_h, g_wqkv_h);
    cudaGetSymbolAddress((void**)&p_w1t_h,  g_w1t_h);
    cudaGetSymbolAddress((void**)&p_w2t_h,  g_w2t_h);

    cudaFuncSetAttribute(gemm_tc, cudaFuncAttributeMaxDynamicSharedMemorySize,
                         GEMM_SMEM);

    dim3 blk(256);
    prep_all<<<PREP_BLOCKS, blk>>>(wq, wk, wv, w1, w2, bq, bk, bv,
                                   p_wqkv_h, p_w1t_h, p_w2t_h, p_bqkv);

    const int MT = S_PAD / 128;   // 10
    for (int l = 0; l < NLAYERS; ++l) {
        size_t oD = (size_t)l * D_MODEL;
        size_t oF = (size_t)l * FF_DIM;

        if (l == 0)
            ln_kernel<<<S_LEN, blk>>>(x, lnin_s, lnin_b, p_hn, p_hn_h);

        // fused QKV, full K: BN=64, grid 10x24 = 240; fp16 output (+bias)
        gemm_tc<<<dim3(MT, QKV_N / 64), blk, GEMM_SMEM>>>(
            p_hn_h, p_wqkv_h + (size_t)l * QKV_N * 512,
            p_bqkv + (size_t)l * QKV_N, nullptr,
            nullptr, nullptr, p_qkv_h, 512, 512, QKV_N);
        // chunked sparse attention v7 (+ residual onto hn)
        attn_chunk_kernel<<<dim3(32, 8), ATTN_THREADS>>>(p_qkv_h, p_hn, p_attn);
        // ln1 -> y fp16
        ln_kernel<<<S_LEN, blk>>>(p_attn, ln1_s + oD, ln1_b + oD,
                                  nullptr, p_y_h);
        // FFN1: BN=64, full K, grid 10x32 = 320
        gemm_tc<<<dim3(MT, FF_DIM / 64), blk, GEMM_SMEM>>>(
            p_y_h, p_w1t_h + (size_t)l * FF_DIM * 512,
            b1 + oF, nullptr,
            nullptr, nullptr, p_ff_h, 512, 512, FF_DIM);
        // FFN2: BN=64, split-K=4, grid 10x8x4 = 320
        gemm_tc<<<dim3(MT, D_MODEL / 64, 4), blk, GEMM_SMEM>>>(
            p_ff_h, p_w2t_h + (size_t)l * D_MODEL * FF_DIM,
            b2 + oD, p_attn,
            p_ff2a, p_ff2b, nullptr, 512, FF_DIM, D_MODEL);
        if (l < NLAYERS - 1) {
            ln2_lnin_kernel<<<S_LEN, blk>>>(
                p_ff2a, p_ff2b, ln2_s + oD, ln2_b + oD, nullptr,
                lnin_s + oD + D_MODEL, lnin_b + oD + D_MODEL,
                p_hn, p_hn_h);
        } else {
            ln2_lnin_kernel<<<S_LEN, blk>>>(
                p_ff2a, p_ff2b, ln2_s + oD, ln2_b + oD, out,
                nullptr, nullptr, nullptr, nullptr);
        }
    }
}